// round 1
// baseline (speedup 1.0000x reference)
#include <cuda_runtime.h>

#define NN 50000
#define NE 640000
#define DD 128

// ---------------- scratch (no allocations allowed) ----------------
__device__ float g_agg[(size_t)NN * DD];   // segment-sum of edge messages
__device__ float g_cnt[NN];                // per-node edge count
__device__ int   g_is64;                   // edge_index dtype flag

// Shared-memory layout (floats):
//   As : [32][65]   staged A chunk (k-major, padded)        offset 0     (2080)
//   Bs : [32][128]  staged weight chunk                     offset 2080  (4096)
//   Hs : [64][132]  hidden activations (padded)             offset 6176  (8448)
//   idx: 2x64 ints / 64 floats                              offset 14624
#define AS_OFF 0
#define BS_OFF 2080
#define HS_OFF 6176
#define IX_OFF 14624
#define SMEM_FLOATS 14752
#define SMEM_BYTES (SMEM_FLOATS * 4)

extern __shared__ float smem[];

// ---------------- utility kernels ----------------
__global__ void zero_kernel() {
    size_t stride = (size_t)gridDim.x * blockDim.x;
    for (size_t i = (size_t)blockIdx.x * blockDim.x + threadIdx.x;
         i < (size_t)NN * DD; i += stride) {
        g_agg[i] = 0.0f;
        if (i < NN) g_cnt[i] = 0.0f;
    }
}

__global__ void detect_kernel(const int* ei32) {
    // int64 little-endian: high word of every value is 0 (indices < 2^31).
    // int32 data: odd words are random indices; 128 consecutive zeros is impossible.
    if (threadIdx.x == 0 && blockIdx.x == 0) {
        int is64 = 1;
        for (int i = 0; i < 128; i++) {
            if (ei32[2 * i + 1] != 0) { is64 = 0; break; }
        }
        g_is64 = is64;
    }
}

__device__ __forceinline__ long long load_idx(const void* ei, long long pos, int is64) {
    return is64 ? ((const long long*)ei)[pos]
                : (long long)((const int*)ei)[pos];
}

// ---------------- edge MLP + scatter ----------------
// edge_out = relu(concat(x[row], x[col], ea) @ We1 + be1) @ We2 + be2
// plus atomic segment-sum into g_agg / g_cnt.
// Tile: 64 edges x 128 cols, 256 threads, 4x8 regs/thread.
__global__ void __launch_bounds__(256) edge_kernel(
    const float* __restrict__ x, const void* __restrict__ ei,
    const float* __restrict__ ea,
    const float* __restrict__ We1, const float* __restrict__ be1,
    const float* __restrict__ We2, const float* __restrict__ be2,
    float* __restrict__ edge_out)
{
    float* As = smem + AS_OFF;
    float* Bs = smem + BS_OFF;
    float* Hs = smem + HS_OFF;
    int*   rs = (int*)(smem + IX_OFF);
    int*   cs = rs + 64;

    const int tid = threadIdx.x;
    const long long e0 = (long long)blockIdx.x * 64;
    const int is64 = g_is64;

    if (tid < 64) {
        rs[tid] = (int)load_idx(ei, e0 + tid, is64);
        cs[tid] = (int)load_idx(ei, (long long)NE + e0 + tid, is64);
    }
    __syncthreads();

    const int tx = tid & 15, ty = tid >> 4;
    const int m0 = ty * 4, n0 = tx * 8;

    float acc[4][8];
    #pragma unroll
    for (int r = 0; r < 4; r++)
        #pragma unroll
        for (int c = 0; c < 8; c++) acc[r][c] = 0.0f;

    // ---- GEMM1: [64 x 384] @ We1[384 x 128] ----
    for (int kc = 0; kc < 12; kc++) {
        const int k0 = kc * 32;
        #pragma unroll
        for (int i = tid; i < 512; i += 256) {
            const int m = i >> 3, f = i & 7;
            const int k = k0 + f * 4;
            float4 v;
            if (k < 128)       v = *(const float4*)(x  + (size_t)rs[m] * DD + k);
            else if (k < 256)  v = *(const float4*)(x  + (size_t)cs[m] * DD + (k - 128));
            else               v = *(const float4*)(ea + (size_t)(e0 + m) * DD + (k - 256));
            As[(f * 4 + 0) * 65 + m] = v.x;
            As[(f * 4 + 1) * 65 + m] = v.y;
            As[(f * 4 + 2) * 65 + m] = v.z;
            As[(f * 4 + 3) * 65 + m] = v.w;
        }
        #pragma unroll
        for (int i = tid; i < 1024; i += 256) {
            const int kr = i >> 5, c4 = i & 31;
            *(float4*)(Bs + kr * 128 + c4 * 4) =
                *(const float4*)(We1 + (size_t)(k0 + kr) * 128 + c4 * 4);
        }
        __syncthreads();
        #pragma unroll
        for (int kk = 0; kk < 32; kk++) {
            float a[4];
            #pragma unroll
            for (int r = 0; r < 4; r++) a[r] = As[kk * 65 + m0 + r];
            const float4 b0 = *(const float4*)(Bs + kk * 128 + n0);
            const float4 b1 = *(const float4*)(Bs + kk * 128 + n0 + 4);
            const float b[8] = {b0.x, b0.y, b0.z, b0.w, b1.x, b1.y, b1.z, b1.w};
            #pragma unroll
            for (int r = 0; r < 4; r++)
                #pragma unroll
                for (int c = 0; c < 8; c++)
                    acc[r][c] = fmaf(a[r], b[c], acc[r][c]);
        }
        __syncthreads();
    }

    // bias + relu -> Hs
    #pragma unroll
    for (int r = 0; r < 4; r++)
        #pragma unroll
        for (int c = 0; c < 8; c++) {
            float v = acc[r][c] + __ldg(be1 + n0 + c);
            Hs[(m0 + r) * 132 + n0 + c] = fmaxf(v, 0.0f);
        }
    __syncthreads();

    // ---- GEMM2: Hs[64 x 128] @ We2[128 x 128] ----
    float acc2[4][8];
    #pragma unroll
    for (int r = 0; r < 4; r++)
        #pragma unroll
        for (int c = 0; c < 8; c++) acc2[r][c] = 0.0f;

    for (int kc = 0; kc < 4; kc++) {
        const int k0 = kc * 32;
        #pragma unroll
        for (int i = tid; i < 1024; i += 256) {
            const int kr = i >> 5, c4 = i & 31;
            *(float4*)(Bs + kr * 128 + c4 * 4) =
                *(const float4*)(We2 + (size_t)(k0 + kr) * 128 + c4 * 4);
        }
        __syncthreads();
        #pragma unroll
        for (int kk = 0; kk < 32; kk++) {
            float a[4];
            #pragma unroll
            for (int r = 0; r < 4; r++) a[r] = Hs[(m0 + r) * 132 + k0 + kk];
            const float4 b0 = *(const float4*)(Bs + kk * 128 + n0);
            const float4 b1 = *(const float4*)(Bs + kk * 128 + n0 + 4);
            const float b[8] = {b0.x, b0.y, b0.z, b0.w, b1.x, b1.y, b1.z, b1.w};
            #pragma unroll
            for (int r = 0; r < 4; r++)
                #pragma unroll
                for (int c = 0; c < 8; c++)
                    acc2[r][c] = fmaf(a[r], b[c], acc2[r][c]);
        }
        __syncthreads();
    }

    // epilogue: bias, store edge_out, atomic scatter into g_agg
    #pragma unroll
    for (int r = 0; r < 4; r++) {
        const int m = m0 + r;
        const long long e = e0 + m;
        const int rw = rs[m];
        float o[8];
        #pragma unroll
        for (int c = 0; c < 8; c++) o[c] = acc2[r][c] + __ldg(be2 + n0 + c);
        *(float4*)(edge_out + (size_t)e * DD + n0)     = make_float4(o[0], o[1], o[2], o[3]);
        *(float4*)(edge_out + (size_t)e * DD + n0 + 4) = make_float4(o[4], o[5], o[6], o[7]);
        #pragma unroll
        for (int c = 0; c < 8; c++)
            atomicAdd(g_agg + (size_t)rw * DD + n0 + c, o[c]);
    }
    if (tid < 64) atomicAdd(g_cnt + rs[tid], 1.0f);
}

// ---------------- node MLP ----------------
// x_out = relu(concat(x, agg/max(cnt,1)) @ Wn1 + bn1) @ Wn2 + bn2
__global__ void __launch_bounds__(256) node_kernel(
    const float* __restrict__ x,
    const float* __restrict__ Wn1, const float* __restrict__ bn1,
    const float* __restrict__ Wn2, const float* __restrict__ bn2,
    float* __restrict__ x_out)
{
    float* As = smem + AS_OFF;
    float* Bs = smem + BS_OFF;
    float* Hs = smem + HS_OFF;
    float* invc = smem + IX_OFF;

    const int tid = threadIdx.x;
    const long long nb = (long long)blockIdx.x * 64;

    if (tid < 64) {
        const long long nd = nb + tid;
        invc[tid] = (nd < NN) ? 1.0f / fmaxf(g_cnt[nd], 1.0f) : 0.0f;
    }
    __syncthreads();

    const int tx = tid & 15, ty = tid >> 4;
    const int m0 = ty * 4, n0 = tx * 8;

    float acc[4][8];
    #pragma unroll
    for (int r = 0; r < 4; r++)
        #pragma unroll
        for (int c = 0; c < 8; c++) acc[r][c] = 0.0f;

    // ---- GEMM1: [64 x 256] @ Wn1[256 x 128] ----
    for (int kc = 0; kc < 8; kc++) {
        const int k0 = kc * 32;
        #pragma unroll
        for (int i = tid; i < 512; i += 256) {
            const int m = i >> 3, f = i & 7;
            const int k = k0 + f * 4;
            const long long nd = nb + m;
            float4 v = make_float4(0.f, 0.f, 0.f, 0.f);
            if (nd < NN) {
                if (k < 128) {
                    v = *(const float4*)(x + (size_t)nd * DD + k);
                } else {
                    v = *(const float4*)(g_agg + (size_t)nd * DD + (k - 128));
                    const float ic = invc[m];
                    v.x *= ic; v.y *= ic; v.z *= ic; v.w *= ic;
                }
            }
            As[(f * 4 + 0) * 65 + m] = v.x;
            As[(f * 4 + 1) * 65 + m] = v.y;
            As[(f * 4 + 2) * 65 + m] = v.z;
            As[(f * 4 + 3) * 65 + m] = v.w;
        }
        #pragma unroll
        for (int i = tid; i < 1024; i += 256) {
            const int kr = i >> 5, c4 = i & 31;
            *(float4*)(Bs + kr * 128 + c4 * 4) =
                *(const float4*)(Wn1 + (size_t)(k0 + kr) * 128 + c4 * 4);
        }
        __syncthreads();
        #pragma unroll
        for (int kk = 0; kk < 32; kk++) {
            float a[4];
            #pragma unroll
            for (int r = 0; r < 4; r++) a[r] = As[kk * 65 + m0 + r];
            const float4 b0 = *(const float4*)(Bs + kk * 128 + n0);
            const float4 b1 = *(const float4*)(Bs + kk * 128 + n0 + 4);
            const float b[8] = {b0.x, b0.y, b0.z, b0.w, b1.x, b1.y, b1.z, b1.w};
            #pragma unroll
            for (int r = 0; r < 4; r++)
                #pragma unroll
                for (int c = 0; c < 8; c++)
                    acc[r][c] = fmaf(a[r], b[c], acc[r][c]);
        }
        __syncthreads();
    }

    #pragma unroll
    for (int r = 0; r < 4; r++)
        #pragma unroll
        for (int c = 0; c < 8; c++) {
            float v = acc[r][c] + __ldg(bn1 + n0 + c);
            Hs[(m0 + r) * 132 + n0 + c] = fmaxf(v, 0.0f);
        }
    __syncthreads();

    // ---- GEMM2: Hs[64 x 128] @ Wn2[128 x 128] ----
    float acc2[4][8];
    #pragma unroll
    for (int r = 0; r < 4; r++)
        #pragma unroll
        for (int c = 0; c < 8; c++) acc2[r][c] = 0.0f;

    for (int kc = 0; kc < 4; kc++) {
        const int k0 = kc * 32;
        #pragma unroll
        for (int i = tid; i < 1024; i += 256) {
            const int kr = i >> 5, c4 = i & 31;
            *(float4*)(Bs + kr * 128 + c4 * 4) =
                *(const float4*)(Wn2 + (size_t)(k0 + kr) * 128 + c4 * 4);
        }
        __syncthreads();
        #pragma unroll
        for (int kk = 0; kk < 32; kk++) {
            float a[4];
            #pragma unroll
            for (int r = 0; r < 4; r++) a[r] = Hs[(m0 + r) * 132 + k0 + kk];
            const float4 b0 = *(const float4*)(Bs + kk * 128 + n0);
            const float4 b1 = *(const float4*)(Bs + kk * 128 + n0 + 4);
            const float b[8] = {b0.x, b0.y, b0.z, b0.w, b1.x, b1.y, b1.z, b1.w};
            #pragma unroll
            for (int r = 0; r < 4; r++)
                #pragma unroll
                for (int c = 0; c < 8; c++)
                    acc2[r][c] = fmaf(a[r], b[c], acc2[r][c]);
        }
        __syncthreads();
    }

    #pragma unroll
    for (int r = 0; r < 4; r++) {
        const long long nd = nb + m0 + r;
        if (nd < NN) {
            float o[8];
            #pragma unroll
            for (int c = 0; c < 8; c++) o[c] = acc2[r][c] + __ldg(bn2 + n0 + c);
            *(float4*)(x_out + (size_t)nd * DD + n0)     = make_float4(o[0], o[1], o[2], o[3]);
            *(float4*)(x_out + (size_t)nd * DD + n0 + 4) = make_float4(o[4], o[5], o[6], o[7]);
        }
    }
}

// ---------------- launch ----------------
extern "C" void kernel_launch(void* const* d_in, const int* in_sizes, int n_in,
                              void* d_out, int out_size) {
    const float* x   = (const float*)d_in[0];
    const void*  ei  = d_in[1];                 // int32 or int64, detected on device
    const float* ea  = (const float*)d_in[2];
    const float* We1 = (const float*)d_in[3];
    const float* be1 = (const float*)d_in[4];
    const float* We2 = (const float*)d_in[5];
    const float* be2 = (const float*)d_in[6];
    const float* Wn1 = (const float*)d_in[7];
    const float* bn1 = (const float*)d_in[8];
    const float* Wn2 = (const float*)d_in[9];
    const float* bn2 = (const float*)d_in[10];

    float* out      = (float*)d_out;
    float* x_out    = out;                          // [NN, DD]
    float* edge_out = out + (size_t)NN * DD;        // [NE, DD]

    cudaFuncSetAttribute(edge_kernel, cudaFuncAttributeMaxDynamicSharedMemorySize, SMEM_BYTES);
    cudaFuncSetAttribute(node_kernel, cudaFuncAttributeMaxDynamicSharedMemorySize, SMEM_BYTES);

    detect_kernel<<<1, 32>>>((const int*)ei);
    zero_kernel<<<2048, 256>>>();
    edge_kernel<<<NE / 64, 256, SMEM_BYTES>>>(x, ei, ea, We1, be1, We2, be2, edge_out);
    node_kernel<<<(NN + 63) / 64, 256, SMEM_BYTES>>>(x, Wn1, bn1, Wn2, bn2, x_out);
}

// round 6
// speedup vs baseline: 3.2103x; 3.2103x over previous
#include <cuda_runtime.h>
#include <cuda_bf16.h>
#include <cstdint>

#define NN 50000
#define NE 640000

// ============================= device scratch =============================
__device__ __align__(16) float g_agg[(size_t)NN * 128];
__device__ float g_cnt[NN];
__device__ int   g_is64;
// pre-transposed + hi/lo-split weights: WT[n][k] = W[k][n]
__device__ __align__(16) __nv_bfloat16 g_W1h[128 * 384], g_W1l[128 * 384];
__device__ __align__(16) __nv_bfloat16 g_W2h[128 * 128], g_W2l[128 * 128];
__device__ __align__(16) __nv_bfloat16 g_N1h[128 * 256], g_N1l[128 * 256];
__device__ __align__(16) __nv_bfloat16 g_N2h[128 * 128], g_N2l[128 * 128];

// ============================= helpers =============================
__device__ __forceinline__ uint32_t smem_to_u32(const void* p) {
    uint32_t a;
    asm("{ .reg .u64 t; cvta.to.shared.u64 t, %1; cvt.u32.u64 %0, t; }" : "=r"(a) : "l"(p));
    return a;
}

__device__ __forceinline__ void ldsm4(uint32_t* r, uint32_t addr) {
    asm volatile("ldmatrix.sync.aligned.m8n8.x4.shared.b16 {%0,%1,%2,%3}, [%4];"
                 : "=r"(r[0]), "=r"(r[1]), "=r"(r[2]), "=r"(r[3]) : "r"(addr));
}

__device__ __forceinline__ void mma16816(float* c, const uint32_t* a,
                                         uint32_t b0, uint32_t b1) {
    asm volatile(
        "mma.sync.aligned.m16n8k16.row.col.f32.bf16.bf16.f32 "
        "{%0,%1,%2,%3}, {%4,%5,%6,%7}, {%8,%9}, {%0,%1,%2,%3};"
        : "+f"(c[0]), "+f"(c[1]), "+f"(c[2]), "+f"(c[3])
        : "r"(a[0]), "r"(a[1]), "r"(a[2]), "r"(a[3]), "r"(b0), "r"(b1));
}

__device__ __forceinline__ void split2(float a, float b, uint32_t& hw, uint32_t& lw) {
    __nv_bfloat16 ah = __float2bfloat16(a);
    __nv_bfloat16 bh = __float2bfloat16(b);
    __nv_bfloat16 al = __float2bfloat16(a - __bfloat162float(ah));
    __nv_bfloat16 bl = __float2bfloat16(b - __bfloat162float(bh));
    __nv_bfloat162 h2; h2.x = ah; h2.y = bh;
    __nv_bfloat162 l2; l2.x = al; l2.y = bl;
    hw = *reinterpret_cast<uint32_t*>(&h2);
    lw = *reinterpret_cast<uint32_t*>(&l2);
}

__device__ __forceinline__ long long load_idx(const void* ei, long long pos, int is64) {
    return is64 ? ((const long long*)ei)[pos] : (long long)((const int*)ei)[pos];
}

// ============================= SMEM layout (bytes) =============================
// header
#define SM_RS   0        // 128 ints
#define SM_CS   512      // 128 ints (edge) / invc floats (node)
#define SM_B1   1024     // bias1 [128] f32
#define SM_B2   1536     // bias2 [128] f32
// panels: [128 rows][72 halves stride] bf16  => 18432 B each
#define PSTR    72
#define PBYTES  (128 * PSTR * 2)
#define P0H     4096
#define P0L     (P0H + PBYTES)
#define P1H     (P0L + PBYTES)
#define P1L     (P1H + PBYTES)
#define P2H     (P1L + PBYTES)
#define P2L     (P2H + PBYTES)
#define SMEM_TOTAL (P2L + PBYTES)    // 114688

// ============================= utility kernels =============================
__global__ void zero_kernel() {
    size_t stride = (size_t)gridDim.x * blockDim.x;
    for (size_t i = (size_t)blockIdx.x * blockDim.x + threadIdx.x;
         i < (size_t)NN * 128; i += stride) {
        g_agg[i] = 0.0f;
        if (i < NN) g_cnt[i] = 0.0f;
    }
}

__global__ void detect_kernel(const int* ei32) {
    if (threadIdx.x == 0 && blockIdx.x == 0) {
        int is64 = 1;
        for (int i = 0; i < 128; i++)
            if (ei32[2 * i + 1] != 0) { is64 = 0; break; }
        g_is64 = is64;
    }
}

__device__ __forceinline__ void split_store(__nv_bfloat16* dh, __nv_bfloat16* dl, float v) {
    __nv_bfloat16 h = __float2bfloat16(v);
    *dh = h;
    *dl = __float2bfloat16(v - __bfloat162float(h));
}

__global__ void prep_kernel(const float* We1, const float* We2,
                            const float* Wn1, const float* Wn2) {
    int i = blockIdx.x * blockDim.x + threadIdx.x;
    if (i < 49152) {                       // We1 [384][128] -> WT [128][384]
        int k = i / 128, n = i % 128;
        split_store(&g_W1h[n * 384 + k], &g_W1l[n * 384 + k], We1[i]);
    } else if (i < 65536) {                // We2 [128][128]
        int j = i - 49152; int k = j / 128, n = j % 128;
        split_store(&g_W2h[n * 128 + k], &g_W2l[n * 128 + k], We2[j]);
    } else if (i < 98304) {                // Wn1 [256][128]
        int j = i - 65536; int k = j / 128, n = j % 128;
        split_store(&g_N1h[n * 256 + k], &g_N1l[n * 256 + k], Wn1[j]);
    } else if (i < 114688) {               // Wn2 [128][128]
        int j = i - 98304; int k = j / 128, n = j % 128;
        split_store(&g_N2h[n * 128 + k], &g_N2l[n * 128 + k], Wn2[j]);
    }
}

// ============================= GEMM slab (K=64) via mma.sync =============================
// A panel [128 m][72k] at aH/aL; B panel [128 n][72k] at bH/bL (both bf16 hi/lo).
// acc[4 mt][4 na][4] accumulates 64m x 32n warp tile.
// 3 passes: Ah*Bh + Ah*Bl + Al*Bh.
__device__ __forceinline__ void gemm_slab(
    float acc[4][4][4], uint32_t smb,
    uint32_t aH, uint32_t aL, uint32_t bH, uint32_t bL,
    int m0, int n0, int rowA, int kA, int rowB, int kB)
{
    #pragma unroll
    for (int k16 = 0; k16 < 4; k16++) {
        const int kk = k16 * 16;
        uint32_t ah[4][4], bhv[2][4], blv[2][4];
        #pragma unroll
        for (int mt = 0; mt < 4; mt++)
            ldsm4(ah[mt], smb + aH + (uint32_t)(((m0 + mt * 16 + rowA) * PSTR + kk + kA) * 2));
        #pragma unroll
        for (int np = 0; np < 2; np++) {
            ldsm4(bhv[np], smb + bH + (uint32_t)(((n0 + np * 16 + rowB) * PSTR + kk + kB) * 2));
            ldsm4(blv[np], smb + bL + (uint32_t)(((n0 + np * 16 + rowB) * PSTR + kk + kB) * 2));
        }
        #pragma unroll
        for (int mt = 0; mt < 4; mt++)
            #pragma unroll
            for (int na = 0; na < 4; na++)
                mma16816(acc[mt][na], ah[mt], bhv[na >> 1][(na & 1) * 2], bhv[na >> 1][(na & 1) * 2 + 1]);
        #pragma unroll
        for (int mt = 0; mt < 4; mt++)
            #pragma unroll
            for (int na = 0; na < 4; na++)
                mma16816(acc[mt][na], ah[mt], blv[na >> 1][(na & 1) * 2], blv[na >> 1][(na & 1) * 2 + 1]);
        #pragma unroll
        for (int mt = 0; mt < 4; mt++)
            ldsm4(ah[mt], smb + aL + (uint32_t)(((m0 + mt * 16 + rowA) * PSTR + kk + kA) * 2));
        #pragma unroll
        for (int mt = 0; mt < 4; mt++)
            #pragma unroll
            for (int na = 0; na < 4; na++)
                mma16816(acc[mt][na], ah[mt], bhv[na >> 1][(na & 1) * 2], bhv[na >> 1][(na & 1) * 2 + 1]);
    }
}

// ============================= fused MLP kernel =============================
template <bool IS_EDGE>
__global__ void __launch_bounds__(256, 2) mlp_kernel(
    const float* __restrict__ x, const void* __restrict__ ei,
    const float* __restrict__ ea,
    const float* __restrict__ b1v, const float* __restrict__ b2v,
    float* __restrict__ outp)
{
    extern __shared__ char smc[];
    const uint32_t smb = smem_to_u32(smc);
    const int tid = threadIdx.x;
    const int wid = tid >> 5, lane = tid & 31;
    const long long r0 = (long long)blockIdx.x * 128;

    int*   rs   = (int*)(smc + SM_RS);
    int*   cs   = (int*)(smc + SM_CS);
    float* invc = (float*)(smc + SM_CS);
    float* sb1  = (float*)(smc + SM_B1);
    float* sb2  = (float*)(smc + SM_B2);
    if (tid < 128) {
        sb1[tid] = b1v[tid];
        sb2[tid] = b2v[tid];
        if (IS_EDGE) {
            const int is64 = g_is64;
            rs[tid] = (int)load_idx(ei, r0 + tid, is64);
            cs[tid] = (int)load_idx(ei, (long long)NE + r0 + tid, is64);
        } else {
            long long nd = r0 + tid; if (nd > NN - 1) nd = NN - 1;
            invc[tid] = 1.0f / fmaxf(g_cnt[nd], 1.0f);
        }
    }
    __syncthreads();

    // ---- staging coords: each thread stages 32 halves of one row (2 thr/row)
    const int srow = tid >> 1, shalf = (tid & 1) * 32;
    // ---- warp tiling: 2x4 warp grid, warp tile 64m x 32n
    const int m0 = (wid >> 2) * 64, n0 = (wid & 3) * 32;
    const int rowA = (lane & 7) + 8 * ((lane >> 3) & 1), kA = 8 * (lane >> 4);
    const int rowB = (lane & 7) + 8 * ((lane >> 4) & 1), kB = 8 * ((lane >> 3) & 1);
    const int g = lane >> 2, t = lane & 3;

    float acc[4][4][4];
    #pragma unroll
    for (int a = 0; a < 4; a++)
        #pragma unroll
        for (int b = 0; b < 4; b++)
            #pragma unroll
            for (int c = 0; c < 4; c++) acc[a][b][c] = 0.0f;

    // ---------------- GEMM1 over K slabs of 64 ----------------
    const int NS1 = IS_EDGE ? 6 : 4;
    for (int s = 0; s < NS1; s++) {
        // stage A slab -> P0 (gather f32, split hi/lo)
        {
            const float* rowp;
            float scale = 1.0f;
            if (IS_EDGE) {
                if (s < 2)      rowp = x  + (size_t)rs[srow] * 128 + s * 64;
                else if (s < 4) rowp = x  + (size_t)cs[srow] * 128 + (s - 2) * 64;
                else            rowp = ea + (size_t)(r0 + srow) * 128 + (s - 4) * 64;
            } else {
                long long nd = r0 + srow; if (nd > NN - 1) nd = NN - 1;
                if (s < 2) rowp = x + (size_t)nd * 128 + s * 64;
                else { rowp = g_agg + (size_t)nd * 128 + (s - 2) * 64; scale = invc[srow]; }
            }
            const float4* p = (const float4*)(rowp + shalf);
            uint32_t hw[16], lw[16];
            #pragma unroll
            for (int j = 0; j < 8; j++) {
                float4 v = p[j];
                split2(v.x * scale, v.y * scale, hw[2 * j],     lw[2 * j]);
                split2(v.z * scale, v.w * scale, hw[2 * j + 1], lw[2 * j + 1]);
            }
            const int off = (srow * PSTR + shalf) * 2;
            #pragma unroll
            for (int qq = 0; qq < 4; qq++) {
                *(uint4*)(smc + P0H + off + qq * 16) =
                    make_uint4(hw[4 * qq], hw[4 * qq + 1], hw[4 * qq + 2], hw[4 * qq + 3]);
                *(uint4*)(smc + P0L + off + qq * 16) =
                    make_uint4(lw[4 * qq], lw[4 * qq + 1], lw[4 * qq + 2], lw[4 * qq + 3]);
            }
        }
        // stage B slab -> P1 (straight copy of pre-split transposed weights)
        // 32 halves per thread = 4 uint4 per panel  (R5 bug: only 2 were staged)
        {
            const __nv_bfloat16 *wh, *wl; int KW;
            if (IS_EDGE) { wh = g_W1h; wl = g_W1l; KW = 384; }
            else         { wh = g_N1h; wl = g_N1l; KW = 256; }
            const int k0 = s * 64;
            const uint4* ph = (const uint4*)(wh + (size_t)srow * KW + k0 + shalf);
            const uint4* pl = (const uint4*)(wl + (size_t)srow * KW + k0 + shalf);
            uint4 h[4], l[4];
            #pragma unroll
            for (int qq = 0; qq < 4; qq++) { h[qq] = ph[qq]; l[qq] = pl[qq]; }
            const int off = (srow * PSTR + shalf) * 2;
            #pragma unroll
            for (int qq = 0; qq < 4; qq++) {
                *(uint4*)(smc + P1H + off + qq * 16) = h[qq];
                *(uint4*)(smc + P1L + off + qq * 16) = l[qq];
            }
        }
        __syncthreads();
        gemm_slab(acc, smb, P0H, P0L, P1H, P1L, m0, n0, rowA, kA, rowB, kB);
        __syncthreads();
    }

    // ---------------- hidden: bias+relu -> split -> panels (k<64:P2, k>=64:P0) ----------------
    #pragma unroll
    for (int mt = 0; mt < 4; mt++) {
        const int r1 = m0 + mt * 16 + g, r2 = r1 + 8;
        #pragma unroll
        for (int na = 0; na < 4; na++) {
            const int c = n0 + na * 8 + 2 * t;
            float h00 = fmaxf(acc[mt][na][0] + sb1[c],     0.0f);
            float h01 = fmaxf(acc[mt][na][1] + sb1[c + 1], 0.0f);
            float h10 = fmaxf(acc[mt][na][2] + sb1[c],     0.0f);
            float h11 = fmaxf(acc[mt][na][3] + sb1[c + 1], 0.0f);
            uint32_t hw0, lw0, hw1, lw1;
            split2(h00, h01, hw0, lw0);
            split2(h10, h11, hw1, lw1);
            const int ph = (c < 64) ? P2H : P0H;
            const int pl = (c < 64) ? P2L : P0L;
            const int cc = c & 63;
            *(uint32_t*)(smc + ph + (r1 * PSTR + cc) * 2) = hw0;
            *(uint32_t*)(smc + pl + (r1 * PSTR + cc) * 2) = lw0;
            *(uint32_t*)(smc + ph + (r2 * PSTR + cc) * 2) = hw1;
            *(uint32_t*)(smc + pl + (r2 * PSTR + cc) * 2) = lw1;
            acc[mt][na][0] = acc[mt][na][1] = acc[mt][na][2] = acc[mt][na][3] = 0.0f;
        }
    }
    // stage GEMM2 B slab0 -> P1 (full 32 halves per thread)
    {
        const __nv_bfloat16 *wh = IS_EDGE ? g_W2h : g_N2h;
        const __nv_bfloat16 *wl = IS_EDGE ? g_W2l : g_N2l;
        const uint4* ph = (const uint4*)(wh + (size_t)srow * 128 + shalf);
        const uint4* pl = (const uint4*)(wl + (size_t)srow * 128 + shalf);
        uint4 h[4], l[4];
        #pragma unroll
        for (int qq = 0; qq < 4; qq++) { h[qq] = ph[qq]; l[qq] = pl[qq]; }
        const int off = (srow * PSTR + shalf) * 2;
        #pragma unroll
        for (int qq = 0; qq < 4; qq++) {
            *(uint4*)(smc + P1H + off + qq * 16) = h[qq];
            *(uint4*)(smc + P1L + off + qq * 16) = l[qq];
        }
    }
    __syncthreads();
    gemm_slab(acc, smb, P2H, P2L, P1H, P1L, m0, n0, rowA, kA, rowB, kB);
    __syncthreads();
    // stage GEMM2 B slab1 -> P1 (full 32 halves per thread)
    {
        const __nv_bfloat16 *wh = IS_EDGE ? g_W2h : g_N2h;
        const __nv_bfloat16 *wl = IS_EDGE ? g_W2l : g_N2l;
        const uint4* ph = (const uint4*)(wh + (size_t)srow * 128 + 64 + shalf);
        const uint4* pl = (const uint4*)(wl + (size_t)srow * 128 + 64 + shalf);
        uint4 h[4], l[4];
        #pragma unroll
        for (int qq = 0; qq < 4; qq++) { h[qq] = ph[qq]; l[qq] = pl[qq]; }
        const int off = (srow * PSTR + shalf) * 2;
        #pragma unroll
        for (int qq = 0; qq < 4; qq++) {
            *(uint4*)(smc + P1H + off + qq * 16) = h[qq];
            *(uint4*)(smc + P1L + off + qq * 16) = l[qq];
        }
    }
    __syncthreads();
    gemm_slab(acc, smb, P0H, P0L, P1H, P1L, m0, n0, rowA, kA, rowB, kB);

    // ---------------- epilogue: bias -> store (+ atomic scatter) ----------------
    #pragma unroll
    for (int mt = 0; mt < 4; mt++) {
        const int r1 = m0 + mt * 16 + g, r2 = r1 + 8;
        #pragma unroll
        for (int na = 0; na < 4; na++) {
            const int c = n0 + na * 8 + 2 * t;
            const float b0 = sb2[c], b1 = sb2[c + 1];
            float v00 = acc[mt][na][0] + b0, v01 = acc[mt][na][1] + b1;
            float v10 = acc[mt][na][2] + b0, v11 = acc[mt][na][3] + b1;
            if (IS_EDGE) {
                *(float2*)(outp + (size_t)(r0 + r1) * 128 + c) = make_float2(v00, v01);
                *(float2*)(outp + (size_t)(r0 + r2) * 128 + c) = make_float2(v10, v11);
                float* a1 = g_agg + (size_t)rs[r1] * 128 + c;
                float* a2 = g_agg + (size_t)rs[r2] * 128 + c;
                atomicAdd(a1, v00); atomicAdd(a1 + 1, v01);
                atomicAdd(a2, v10); atomicAdd(a2 + 1, v11);
            } else {
                if (r0 + r1 < NN)
                    *(float2*)(outp + (size_t)(r0 + r1) * 128 + c) = make_float2(v00, v01);
                if (r0 + r2 < NN)
                    *(float2*)(outp + (size_t)(r0 + r2) * 128 + c) = make_float2(v10, v11);
            }
        }
    }
    if (IS_EDGE && (wid & 3) == 0 && t == 0) {
        #pragma unroll
        for (int mt = 0; mt < 4; mt++) {
            atomicAdd(g_cnt + rs[m0 + mt * 16 + g],     1.0f);
            atomicAdd(g_cnt + rs[m0 + mt * 16 + g + 8], 1.0f);
        }
    }
}

// ============================= launch =============================
extern "C" void kernel_launch(void* const* d_in, const int* in_sizes, int n_in,
                              void* d_out, int out_size) {
    const float* x   = (const float*)d_in[0];
    const void*  ei  = d_in[1];
    const float* ea  = (const float*)d_in[2];
    const float* be1 = (const float*)d_in[4];
    const float* be2 = (const float*)d_in[6];
    const float* bn1 = (const float*)d_in[8];
    const float* bn2 = (const float*)d_in[10];

    float* out      = (float*)d_out;
    float* x_out    = out;                       // [NN, 128]
    float* edge_out = out + (size_t)NN * 128;    // [NE, 128]

    cudaFuncSetAttribute(mlp_kernel<true>,  cudaFuncAttributeMaxDynamicSharedMemorySize, SMEM_TOTAL);
    cudaFuncSetAttribute(mlp_kernel<false>, cudaFuncAttributeMaxDynamicSharedMemorySize, SMEM_TOTAL);

    detect_kernel<<<1, 32>>>((const int*)ei);
    zero_kernel<<<2048, 256>>>();
    prep_kernel<<<448, 256>>>((const float*)d_in[3], (const float*)d_in[5],
                              (const float*)d_in[7], (const float*)d_in[9]);
    mlp_kernel<true><<<NE / 128, 256, SMEM_TOTAL>>>(x, ei, ea, be1, be2, edge_out);
    mlp_kernel<false><<<(NN + 127) / 128, 256, SMEM_TOTAL>>>(x, ei, ea, bn1, bn2, x_out);
}

// round 8
// speedup vs baseline: 3.2316x; 1.0066x over previous
#include <cuda_runtime.h>
#include <cuda_bf16.h>
#include <cstdint>

#define NN 50000
#define NE 640000
#define PSTR 72

// ============================= device scratch =============================
__device__ __align__(16) float g_agg[(size_t)NN * 128];
__device__ float g_cnt[NN];
__device__ int   g_is64;
// pre-transposed + hi/lo-split weights: WT[n][k] = W[k][n]
__device__ __align__(16) __nv_bfloat16 g_W1h[128 * 384], g_W1l[128 * 384];
__device__ __align__(16) __nv_bfloat16 g_W2h[128 * 128], g_W2l[128 * 128];
__device__ __align__(16) __nv_bfloat16 g_N1h[128 * 256], g_N1l[128 * 256];
__device__ __align__(16) __nv_bfloat16 g_N2h[128 * 128], g_N2l[128 * 128];

// ============================= helpers =============================
__device__ __forceinline__ uint32_t smem_to_u32(const void* p) {
    uint32_t a;
    asm("{ .reg .u64 t; cvta.to.shared.u64 t, %1; cvt.u32.u64 %0, t; }" : "=r"(a) : "l"(p));
    return a;
}
__device__ __forceinline__ void ldsm4(uint32_t* r, uint32_t addr) {
    asm volatile("ldmatrix.sync.aligned.m8n8.x4.shared.b16 {%0,%1,%2,%3}, [%4];"
                 : "=r"(r[0]), "=r"(r[1]), "=r"(r[2]), "=r"(r[3]) : "r"(addr));
}
__device__ __forceinline__ void mma16816(float* c, const uint32_t* a,
                                         uint32_t b0, uint32_t b1) {
    asm volatile(
        "mma.sync.aligned.m16n8k16.row.col.f32.bf16.bf16.f32 "
        "{%0,%1,%2,%3}, {%4,%5,%6,%7}, {%8,%9}, {%0,%1,%2,%3};"
        : "+f"(c[0]), "+f"(c[1]), "+f"(c[2]), "+f"(c[3])
        : "r"(a[0]), "r"(a[1]), "r"(a[2]), "r"(a[3]), "r"(b0), "r"(b1));
}
__device__ __forceinline__ void cpa16(uint32_t dst, const void* src) {
    asm volatile("cp.async.cg.shared.global [%0], [%1], 16;" :: "r"(dst), "l"(src));
}
#define CP_COMMIT asm volatile("cp.async.commit_group;" ::: "memory")
#define CP_WAIT0  asm volatile("cp.async.wait_group 0;"  ::: "memory")
#define SW128(o) ((o) ^ (((o) >> 3) & 0x70))

__device__ __forceinline__ void split2(float a, float b, uint32_t& hw, uint32_t& lw) {
    __nv_bfloat16 ah = __float2bfloat16(a);
    __nv_bfloat16 bh = __float2bfloat16(b);
    __nv_bfloat16 al = __float2bfloat16(a - __bfloat162float(ah));
    __nv_bfloat16 bl = __float2bfloat16(b - __bfloat162float(bh));
    __nv_bfloat162 h2; h2.x = ah; h2.y = bh;
    __nv_bfloat162 l2; l2.x = al; l2.y = bl;
    hw = *reinterpret_cast<uint32_t*>(&h2);
    lw = *reinterpret_cast<uint32_t*>(&l2);
}
__device__ __forceinline__ long long load_idx(const void* ei, long long pos, int is64) {
    return is64 ? ((const long long*)ei)[pos] : (long long)((const int*)ei)[pos];
}

// ============================= SMEM layout (bytes) =============================
#define SM_RS   0            // 256 ints (edge row targets)
#define SM_B1   2048         // bias1 [128] f32
#define SM_B2   2560         // bias2 [128] f32
// A panels: 256 rows x PSTR halves => 36864 B each
#define APH     4096
#define APL     (APH + 36864)        // 40960
// B double buffer: 128 rows x PSTR halves => 18432 B each
#define BP0H    77824
#define BP0L    (BP0H + 18432)       // 96256
#define BP1H    (BP0L + 18432)       // 114688
#define BP1L    (BP1H + 18432)       // 133120
// raw fp32 A slab (256x64 f32, swizzled) / H-k1 panels after GEMM1
#define RAWOFF  151552
#define HK1H    RAWOFF
#define HK1L    (RAWOFF + 36864)
#define SMEM_TOTAL 225280

// ============================= utility kernels =============================
__global__ void zero_kernel() {
    size_t stride = (size_t)gridDim.x * blockDim.x;
    for (size_t i = (size_t)blockIdx.x * blockDim.x + threadIdx.x;
         i < (size_t)NN * 128; i += stride) {
        g_agg[i] = 0.0f;
        if (i < NN) g_cnt[i] = 0.0f;
    }
}
__global__ void detect_kernel(const int* ei32) {
    if (threadIdx.x == 0 && blockIdx.x == 0) {
        int is64 = 1;
        for (int i = 0; i < 128; i++)
            if (ei32[2 * i + 1] != 0) { is64 = 0; break; }
        g_is64 = is64;
    }
}
__device__ __forceinline__ void split_store(__nv_bfloat16* dh, __nv_bfloat16* dl, float v) {
    __nv_bfloat16 h = __float2bfloat16(v);
    *dh = h;
    *dl = __float2bfloat16(v - __bfloat162float(h));
}
__global__ void prep_kernel(const float* We1, const float* We2,
                            const float* Wn1, const float* Wn2) {
    int i = blockIdx.x * blockDim.x + threadIdx.x;
    if (i < 49152) {
        int k = i / 128, n = i % 128;
        split_store(&g_W1h[n * 384 + k], &g_W1l[n * 384 + k], We1[i]);
    } else if (i < 65536) {
        int j = i - 49152; int k = j / 128, n = j % 128;
        split_store(&g_W2h[n * 128 + k], &g_W2l[n * 128 + k], We2[j]);
    } else if (i < 98304) {
        int j = i - 65536; int k = j / 128, n = j % 128;
        split_store(&g_N1h[n * 256 + k], &g_N1l[n * 256 + k], Wn1[j]);
    } else if (i < 114688) {
        int j = i - 98304; int k = j / 128, n = j % 128;
        split_store(&g_N2h[n * 128 + k], &g_N2l[n * 128 + k], Wn2[j]);
    }
}

// ============================= GEMM slab (K=64), warp tile 64x64 =============================
// A panels 256 rows x PSTR; B panels 128 rows x PSTR. 3 passes: Ah*Bh + Ah*Bl + Al*Bh.
__device__ __forceinline__ void gemm_slab64(
    float acc[4][8][4], uint32_t smb,
    uint32_t aH, uint32_t aL, uint32_t bH, uint32_t bL,
    int m0, int n0, int rowA, int kA, int rowB, int kB)
{
    #pragma unroll
    for (int k16 = 0; k16 < 4; k16++) {
        const int kk = k16 * 16;
        uint32_t ah[4][4], bh[4][4], bl[4][4];
        #pragma unroll
        for (int mt = 0; mt < 4; mt++)
            ldsm4(ah[mt], smb + aH + (uint32_t)(((m0 + mt * 16 + rowA) * PSTR + kk + kA) * 2));
        #pragma unroll
        for (int np = 0; np < 4; np++) {
            ldsm4(bh[np], smb + bH + (uint32_t)(((n0 + np * 16 + rowB) * PSTR + kk + kB) * 2));
            ldsm4(bl[np], smb + bL + (uint32_t)(((n0 + np * 16 + rowB) * PSTR + kk + kB) * 2));
        }
        #pragma unroll
        for (int mt = 0; mt < 4; mt++)
            #pragma unroll
            for (int na = 0; na < 8; na++)
                mma16816(acc[mt][na], ah[mt], bh[na >> 1][(na & 1) * 2], bh[na >> 1][(na & 1) * 2 + 1]);
        #pragma unroll
        for (int mt = 0; mt < 4; mt++)
            #pragma unroll
            for (int na = 0; na < 8; na++)
                mma16816(acc[mt][na], ah[mt], bl[na >> 1][(na & 1) * 2], bl[na >> 1][(na & 1) * 2 + 1]);
        #pragma unroll
        for (int mt = 0; mt < 4; mt++)
            ldsm4(ah[mt], smb + aL + (uint32_t)(((m0 + mt * 16 + rowA) * PSTR + kk + kA) * 2));
        #pragma unroll
        for (int mt = 0; mt < 4; mt++)
            #pragma unroll
            for (int na = 0; na < 8; na++)
                mma16816(acc[mt][na], ah[mt], bh[na >> 1][(na & 1) * 2], bh[na >> 1][(na & 1) * 2 + 1]);
    }
}

// ============================= fused MLP kernel =============================
// CTA tile: 256 rows x 128 out. 256 threads, 8 warps (4m x 2n), warp tile 64x64.
// cp.async pipelined staging: raw fp32 A slab + pre-split B panels (double buffered).
template <bool IS_EDGE>
__global__ void __launch_bounds__(256, 1) mlp_kernel(
    const float* __restrict__ x, const void* __restrict__ ei,
    const float* __restrict__ ea,
    const float* __restrict__ b1v, const float* __restrict__ b2v,
    float* __restrict__ outp)
{
    extern __shared__ char smc[];
    const uint32_t smb = smem_to_u32(smc);
    const int tid = threadIdx.x;
    const int wid = tid >> 5, lane = tid & 31;
    const long long r0 = (long long)blockIdx.x * 256;
    const int NS = IS_EDGE ? 6 : 4;

    int*   rs  = (int*)(smc + SM_RS);
    float* sb1 = (float*)(smc + SM_B1);
    float* sb2 = (float*)(smc + SM_B2);

    // per-thread row sources (thread t owns row t of the 256-row tile)
    const float* aBase[3];
    float invc_reg = 1.0f;
    if (IS_EDGE) {
        const int is64 = g_is64;
        long long rr = load_idx(ei, r0 + tid, is64);
        long long cc = load_idx(ei, (long long)NE + r0 + tid, is64);
        rs[tid] = (int)rr;
        aBase[0] = x + (size_t)rr * 128;
        aBase[1] = x + (size_t)cc * 128;
        aBase[2] = ea + (size_t)(r0 + tid) * 128;
    } else {
        long long nd = r0 + tid; if (nd > NN - 1) nd = NN - 1;
        invc_reg = 1.0f / fmaxf(g_cnt[nd], 1.0f);
        aBase[0] = x + (size_t)nd * 128;
        aBase[1] = g_agg + (size_t)nd * 128;
        aBase[2] = g_agg + (size_t)nd * 128;   // unused
    }
    if (tid < 128) { sb1[tid] = b1v[tid]; sb2[tid] = b2v[tid]; }

    // ---- staging lambdas ----
    auto issueRAW = [&](int s) {   // cp.async slab s raw fp32 -> RAW (own row region)
        if (s >= NS) return;
        const float* p = aBase[s >> 1] + (s & 1) * 64;
        #pragma unroll
        for (int seg = 0; seg < 16; seg++)
            cpa16(smb + RAWOFF + SW128(tid * 256 + seg * 16), p + seg * 4);
    };
    auto splitA = [&](int s) {     // RAW holds slab s -> split into A panels
        const float sc = (!IS_EDGE && s >= 2) ? invc_reg : 1.0f;
        #pragma unroll
        for (int seg = 0; seg < 16; seg++) {
            float4 v = *(const float4*)(smc + RAWOFF + SW128(tid * 256 + seg * 16));
            uint32_t h0, l0, h1, l1;
            split2(v.x * sc, v.y * sc, h0, l0);
            split2(v.z * sc, v.w * sc, h1, l1);
            const int ob = tid * (PSTR * 2) + seg * 8;
            *(uint2*)(smc + APH + ob) = make_uint2(h0, h1);
            *(uint2*)(smc + APL + ob) = make_uint2(l0, l1);
        }
    };
    auto stageB = [&](int seq) {   // cp.async weight slab (unified seq) -> buf[seq&1]
        if (seq > NS + 1) return;
        const __nv_bfloat16 *wh, *wl; int KW, koff;
        if (seq < NS) {
            wh = IS_EDGE ? g_W1h : g_N1h; wl = IS_EDGE ? g_W1l : g_N1l;
            KW = IS_EDGE ? 384 : 256; koff = seq * 64;
        } else {
            wh = IS_EDGE ? g_W2h : g_N2h; wl = IS_EDGE ? g_W2l : g_N2l;
            KW = 128; koff = (seq - NS) * 64;
        }
        const int wrow = tid >> 1, part = tid & 1;
        const uint32_t dH = smb + ((seq & 1) ? BP1H : BP0H) + (uint32_t)(wrow * (PSTR * 2) + part * 64);
        const uint32_t dL = smb + ((seq & 1) ? BP1L : BP0L) + (uint32_t)(wrow * (PSTR * 2) + part * 64);
        const size_t so = (size_t)wrow * KW + koff + part * 32;
        #pragma unroll
        for (int j = 0; j < 4; j++) {
            cpa16(dH + j * 16, wh + so + j * 8);
            cpa16(dL + j * 16, wl + so + j * 8);
        }
    };

    // ---- warp tiling ----
    const int m0 = (wid >> 1) * 64, n0 = (wid & 1) * 64;
    const int rowA = (lane & 7) + 8 * ((lane >> 3) & 1), kA = 8 * (lane >> 4);
    const int rowB = (lane & 7) + 8 * ((lane >> 4) & 1), kB = 8 * ((lane >> 3) & 1);
    const int g = lane >> 2, t4 = lane & 3;

    float acc[4][8][4];
    #pragma unroll
    for (int a = 0; a < 4; a++)
        #pragma unroll
        for (int b = 0; b < 8; b++)
            #pragma unroll
            for (int c = 0; c < 4; c++) acc[a][b][c] = 0.0f;

    // ---- prologue: group{RAW0,B0}; wait; split0 + group{RAW1,B1} ----
    issueRAW(0); stageB(0); CP_COMMIT;
    CP_WAIT0;
    splitA(0); issueRAW(1); stageB(1); CP_COMMIT;
    __syncthreads();

    // ---- GEMM1 pipeline ----
    for (int s = 0; s < NS; s++) {
        gemm_slab64(acc, smb, APH, APL,
                    (s & 1) ? BP1H : BP0H, (s & 1) ? BP1L : BP0L,
                    m0, n0, rowA, kA, rowB, kB);
        __syncthreads();
        CP_WAIT0;                       // prior group (RAW s+1, B s+1) landed
        if (s + 1 < NS) { splitA(s + 1); issueRAW(s + 2); }
        stageB(s + 2);
        CP_COMMIT;
        __syncthreads();
    }

    // ---- hidden: bias+relu -> split -> H panels (cols<64: A panels, cols>=64: HK1) ----
    {
        const uint32_t hB = (n0 == 0) ? APH : HK1H;
        const uint32_t lB = (n0 == 0) ? APL : HK1L;
        #pragma unroll
        for (int mt = 0; mt < 4; mt++) {
            const int r1 = m0 + mt * 16 + g, r2 = r1 + 8;
            #pragma unroll
            for (int na = 0; na < 8; na++) {
                const int c = n0 + na * 8 + 2 * t4;
                float h00 = fmaxf(acc[mt][na][0] + sb1[c],     0.0f);
                float h01 = fmaxf(acc[mt][na][1] + sb1[c + 1], 0.0f);
                float h10 = fmaxf(acc[mt][na][2] + sb1[c],     0.0f);
                float h11 = fmaxf(acc[mt][na][3] + sb1[c + 1], 0.0f);
                uint32_t hw0, lw0, hw1, lw1;
                split2(h00, h01, hw0, lw0);
                split2(h10, h11, hw1, lw1);
                const int cc = c & 63;
                *(uint32_t*)(smc + hB + (r1 * PSTR + cc) * 2) = hw0;
                *(uint32_t*)(smc + lB + (r1 * PSTR + cc) * 2) = lw0;
                *(uint32_t*)(smc + hB + (r2 * PSTR + cc) * 2) = hw1;
                *(uint32_t*)(smc + lB + (r2 * PSTR + cc) * 2) = lw1;
                acc[mt][na][0] = acc[mt][na][1] = acc[mt][na][2] = acc[mt][na][3] = 0.0f;
            }
        }
    }
    CP_WAIT0;                           // W2 slab1 group landed
    __syncthreads();

    // ---- GEMM2: H @ W2 (slab0 from A panels + buf[NS&1], slab1 from HK1 + buf[(NS+1)&1]) ----
    gemm_slab64(acc, smb, APH, APL,
                (NS & 1) ? BP1H : BP0H, (NS & 1) ? BP1L : BP0L,
                m0, n0, rowA, kA, rowB, kB);
    gemm_slab64(acc, smb, HK1H, HK1L,
                ((NS + 1) & 1) ? BP1H : BP0H, ((NS + 1) & 1) ? BP1L : BP0L,
                m0, n0, rowA, kA, rowB, kB);

    // ---- epilogue: bias -> store (+ atomic scatter for edge) ----
    #pragma unroll
    for (int mt = 0; mt < 4; mt++) {
        const int r1 = m0 + mt * 16 + g, r2 = r1 + 8;
        #pragma unroll
        for (int na = 0; na < 8; na++) {
            const int c = n0 + na * 8 + 2 * t4;
            const float b0 = sb2[c], b1 = sb2[c + 1];
            float v00 = acc[mt][na][0] + b0, v01 = acc[mt][na][1] + b1;
            float v10 = acc[mt][na][2] + b0, v11 = acc[mt][na][3] + b1;
            if (IS_EDGE) {
                *(float2*)(outp + (size_t)(r0 + r1) * 128 + c) = make_float2(v00, v01);
                *(float2*)(outp + (size_t)(r0 + r2) * 128 + c) = make_float2(v10, v11);
                float* a1 = g_agg + (size_t)rs[r1] * 128 + c;
                float* a2 = g_agg + (size_t)rs[r2] * 128 + c;
                atomicAdd(a1, v00); atomicAdd(a1 + 1, v01);
                atomicAdd(a2, v10); atomicAdd(a2 + 1, v11);
            } else {
                if (r0 + r1 < NN)
                    *(float2*)(outp + (size_t)(r0 + r1) * 128 + c) = make_float2(v00, v01);
                if (r0 + r2 < NN)
                    *(float2*)(outp + (size_t)(r0 + r2) * 128 + c) = make_float2(v10, v11);
            }
        }
    }
    if (IS_EDGE && (wid & 1) == 0 && t4 == 0) {
        #pragma unroll
        for (int mt = 0; mt < 4; mt++) {
            atomicAdd(g_cnt + rs[m0 + mt * 16 + g],     1.0f);
            atomicAdd(g_cnt + rs[m0 + mt * 16 + g + 8], 1.0f);
        }
    }
}

// ============================= launch =============================
extern "C" void kernel_launch(void* const* d_in, const int* in_sizes, int n_in,
                              void* d_out, int out_size) {
    const float* x   = (const float*)d_in[0];
    const void*  ei  = d_in[1];
    const float* ea  = (const float*)d_in[2];
    const float* be1 = (const float*)d_in[4];
    const float* be2 = (const float*)d_in[6];
    const float* bn1 = (const float*)d_in[8];
    const float* bn2 = (const float*)d_in[10];

    float* out      = (float*)d_out;
    float* x_out    = out;                       // [NN, 128]
    float* edge_out = out + (size_t)NN * 128;    // [NE, 128]

    cudaFuncSetAttribute(mlp_kernel<true>,  cudaFuncAttributeMaxDynamicSharedMemorySize, SMEM_TOTAL);
    cudaFuncSetAttribute(mlp_kernel<false>, cudaFuncAttributeMaxDynamicSharedMemorySize, SMEM_TOTAL);

    detect_kernel<<<1, 32>>>((const int*)ei);
    zero_kernel<<<2048, 256>>>();
    prep_kernel<<<448, 256>>>((const float*)d_in[3], (const float*)d_in[5],
                              (const float*)d_in[7], (const float*)d_in[9]);
    mlp_kernel<true><<<NE / 256, 256, SMEM_TOTAL>>>(x, ei, ea, be1, be2, edge_out);
    mlp_kernel<false><<<(NN + 255) / 256, 256, SMEM_TOTAL>>>(x, ei, ea, bn1, bn2, x_out);
}

// round 10
// speedup vs baseline: 4.7281x; 1.4631x over previous
#include <cuda_runtime.h>
#include <cuda_fp16.h>
#include <cstdint>

#define NN 50000
#define NE 640000
#define PSTR 72

// ============================= device scratch =============================
__device__ __align__(16) float g_agg[(size_t)NN * 128];
__device__ float g_cnt[NN];
__device__ int   g_is64;
// pre-transposed fp16 weights: WT[n][k] = (half)W[k][n]
__device__ __align__(16) __half g_W1f[128 * 384];
__device__ __align__(16) __half g_W2f[128 * 128];
__device__ __align__(16) __half g_N1f[128 * 256];
__device__ __align__(16) __half g_N2f[128 * 128];

// ============================= helpers =============================
__device__ __forceinline__ uint32_t smem_to_u32(const void* p) {
    uint32_t a;
    asm("{ .reg .u64 t; cvta.to.shared.u64 t, %1; cvt.u32.u64 %0, t; }" : "=r"(a) : "l"(p));
    return a;
}
__device__ __forceinline__ void ldsm4(uint32_t* r, uint32_t addr) {
    asm volatile("ldmatrix.sync.aligned.m8n8.x4.shared.b16 {%0,%1,%2,%3}, [%4];"
                 : "=r"(r[0]), "=r"(r[1]), "=r"(r[2]), "=r"(r[3]) : "r"(addr));
}
__device__ __forceinline__ void mma16816(float* c, const uint32_t* a,
                                         uint32_t b0, uint32_t b1) {
    asm volatile(
        "mma.sync.aligned.m16n8k16.row.col.f32.f16.f16.f32 "
        "{%0,%1,%2,%3}, {%4,%5,%6,%7}, {%8,%9}, {%0,%1,%2,%3};"
        : "+f"(c[0]), "+f"(c[1]), "+f"(c[2]), "+f"(c[3])
        : "r"(a[0]), "r"(a[1]), "r"(a[2]), "r"(a[3]), "r"(b0), "r"(b1));
}
__device__ __forceinline__ void cpa16(uint32_t dst, const void* src) {
    asm volatile("cp.async.cg.shared.global [%0], [%1], 16;" :: "r"(dst), "l"(src));
}
#define CP_COMMIT asm volatile("cp.async.commit_group;" ::: "memory")
#define CP_WAIT0  asm volatile("cp.async.wait_group 0;"  ::: "memory")
#define SW128(o) ((o) ^ (((o) >> 3) & 0x70))

// fp16 hi/lo split of two floats -> packed half2 words
__device__ __forceinline__ void split2h(float a, float b, uint32_t& hw, uint32_t& lw) {
    __half ah = __float2half(a);
    __half bh = __float2half(b);
    __half al = __float2half(a - __half2float(ah));
    __half bl = __float2half(b - __half2float(bh));
    __half2 h2; h2.x = ah; h2.y = bh;
    __half2 l2; l2.x = al; l2.y = bl;
    hw = *reinterpret_cast<uint32_t*>(&h2);
    lw = *reinterpret_cast<uint32_t*>(&l2);
}
__device__ __forceinline__ long long load_idx(const void* ei, long long pos, int is64) {
    return is64 ? ((const long long*)ei)[pos] : (long long)((const int*)ei)[pos];
}

// ============================= SMEM layout (bytes) =============================
#define SM_RS   0            // 128 ints
#define SM_B1   2048         // bias1 [128] f32
#define SM_B2   2560         // bias2 [128] f32
// A panels (hi/lo fp16): 128 rows x PSTR halves = 18432 B each
#define APH     4096
#define APL     22528
// B single-fp16 double buffer: 128 rows x PSTR halves
#define BP0     40960
#define BP1     59392
// raw fp32 slab: 128 rows x 64 f32, swizzled (also holds H cols 64..127 later)
#define RAWOFF  77824
#define SMEM_TOTAL 110592     // 2 CTAs/SM: 221184 <= 227KB

// ============================= utility kernels =============================
__global__ void zero_kernel() {
    size_t stride = (size_t)gridDim.x * blockDim.x;
    for (size_t i = (size_t)blockIdx.x * blockDim.x + threadIdx.x;
         i < (size_t)NN * 128; i += stride) {
        g_agg[i] = 0.0f;
        if (i < NN) g_cnt[i] = 0.0f;
    }
}
__global__ void detect_kernel(const int* ei32) {
    if (threadIdx.x == 0 && blockIdx.x == 0) {
        int is64 = 1;
        for (int i = 0; i < 128; i++)
            if (ei32[2 * i + 1] != 0) { is64 = 0; break; }
        g_is64 = is64;
    }
}
__global__ void prep_kernel(const float* We1, const float* We2,
                            const float* Wn1, const float* Wn2) {
    int i = blockIdx.x * blockDim.x + threadIdx.x;
    if (i < 49152) {                       // We1 [384][128] -> WT [128][384]
        int k = i / 128, n = i % 128;
        g_W1f[n * 384 + k] = __float2half(We1[i]);
    } else if (i < 65536) {
        int j = i - 49152; int k = j / 128, n = j % 128;
        g_W2f[n * 128 + k] = __float2half(We2[j]);
    } else if (i < 98304) {
        int j = i - 65536; int k = j / 128, n = j % 128;
        g_N1f[n * 256 + k] = __float2half(Wn1[j]);
    } else if (i < 114688) {
        int j = i - 98304; int k = j / 128, n = j % 128;
        g_N2f[n * 128 + k] = __float2half(Wn2[j]);
    }
}

// ============================= GEMM slab (K=64), warp tile 64x32, fp16 2-pass ============
// acc += Ah*B + Al*B   (A panels hi/lo, B single fp16 panel)
__device__ __forceinline__ void gemm_slab32(
    float acc[4][4][4], uint32_t smb,
    uint32_t aH, uint32_t aL, uint32_t bP,
    int m0, int n0, int rowA, int kA, int rowB, int kB)
{
    #pragma unroll
    for (int k16 = 0; k16 < 4; k16++) {
        const int kk = k16 * 16;
        uint32_t ah[4][4], al[4][4], bb[2][4];
        #pragma unroll
        for (int mt = 0; mt < 4; mt++)
            ldsm4(ah[mt], smb + aH + (uint32_t)(((m0 + mt * 16 + rowA) * PSTR + kk + kA) * 2));
        #pragma unroll
        for (int np = 0; np < 2; np++)
            ldsm4(bb[np], smb + bP + (uint32_t)(((n0 + np * 16 + rowB) * PSTR + kk + kB) * 2));
        #pragma unroll
        for (int mt = 0; mt < 4; mt++)
            #pragma unroll
            for (int na = 0; na < 4; na++)
                mma16816(acc[mt][na], ah[mt], bb[na >> 1][(na & 1) * 2], bb[na >> 1][(na & 1) * 2 + 1]);
        #pragma unroll
        for (int mt = 0; mt < 4; mt++)
            ldsm4(al[mt], smb + aL + (uint32_t)(((m0 + mt * 16 + rowA) * PSTR + kk + kA) * 2));
        #pragma unroll
        for (int mt = 0; mt < 4; mt++)
            #pragma unroll
            for (int na = 0; na < 4; na++)
                mma16816(acc[mt][na], al[mt], bb[na >> 1][(na & 1) * 2], bb[na >> 1][(na & 1) * 2 + 1]);
    }
}

// ============================= fused MLP kernel =============================
// CTA: 128 rows x 128 out, 256 thr, 8 warps (2m x 4n), warp tile 64x32, 2 CTAs/SM.
template <bool IS_EDGE>
__global__ void __launch_bounds__(256, 2) mlp_kernel(
    const float* __restrict__ x, const void* __restrict__ ei,
    const float* __restrict__ ea,
    const float* __restrict__ b1v, const float* __restrict__ b2v,
    float* __restrict__ outp)
{
    extern __shared__ char smc[];
    const uint32_t smb = smem_to_u32(smc);
    const int tid = threadIdx.x;
    const int wid = tid >> 5, lane = tid & 31;
    const long long r0 = (long long)blockIdx.x * 128;
    const int NS = IS_EDGE ? 6 : 4;

    int*   rs  = (int*)(smc + SM_RS);
    float* sb1 = (float*)(smc + SM_B1);
    float* sb2 = (float*)(smc + SM_B2);

    // thread pair (tid, tid^1) shares row = tid>>1; half index (tid&1)
    const int row = tid >> 1, hfl = (tid & 1) * 32;   // hfl in f32/half units
    const float* aBase[3];
    float invc_reg = 1.0f;
    if (IS_EDGE) {
        const int is64 = g_is64;
        long long rr = load_idx(ei, r0 + row, is64);
        long long cc = load_idx(ei, (long long)NE + r0 + row, is64);
        rs[row] = (int)rr;
        aBase[0] = x + (size_t)rr * 128;
        aBase[1] = x + (size_t)cc * 128;
        aBase[2] = ea + (size_t)(r0 + row) * 128;
    } else {
        long long nd = r0 + row; if (nd > NN - 1) nd = NN - 1;
        invc_reg = 1.0f / fmaxf(g_cnt[nd], 1.0f);
        aBase[0] = x + (size_t)nd * 128;
        aBase[1] = g_agg + (size_t)nd * 128;
        aBase[2] = g_agg + (size_t)nd * 128;
    }
    if (tid < 128) { sb1[tid] = b1v[tid]; sb2[tid] = b2v[tid]; }

    // ---- staging lambdas ----
    auto issueRAW = [&](int s) {     // raw fp32 slab s -> RAW (swizzled)
        if (s >= NS) return;
        const float* p = aBase[s >> 1] + (s & 1) * 64 + hfl;
        #pragma unroll
        for (int j = 0; j < 8; j++)
            cpa16(smb + RAWOFF + SW128(row * 256 + hfl * 4 + j * 16), p + j * 4);
    };
    auto splitRAW = [&](float sc) {  // RAW -> A hi/lo fp16 panels
        #pragma unroll
        for (int j = 0; j < 4; j++) {
            float4 v0 = *(const float4*)(smc + RAWOFF + SW128(row * 256 + hfl * 4 + j * 32));
            float4 v1 = *(const float4*)(smc + RAWOFF + SW128(row * 256 + hfl * 4 + j * 32 + 16));
            uint32_t h[4], l[4];
            split2h(v0.x * sc, v0.y * sc, h[0], l[0]);
            split2h(v0.z * sc, v0.w * sc, h[1], l[1]);
            split2h(v1.x * sc, v1.y * sc, h[2], l[2]);
            split2h(v1.z * sc, v1.w * sc, h[3], l[3]);
            const int ob = row * (PSTR * 2) + hfl * 2 + j * 16;
            *(uint4*)(smc + APH + ob) = make_uint4(h[0], h[1], h[2], h[3]);
            *(uint4*)(smc + APL + ob) = make_uint4(l[0], l[1], l[2], l[3]);
        }
    };
    auto stageB = [&](int seq) {     // weight slab seq -> buf[seq&1]
        if (seq > NS + 1) return;
        const __half* wf; int KW, koff;
        if (seq < NS) {
            wf = IS_EDGE ? g_W1f : g_N1f;
            KW = IS_EDGE ? 384 : 256; koff = seq * 64;
        } else {
            wf = IS_EDGE ? g_W2f : g_N2f;
            KW = 128; koff = (seq - NS) * 64;
        }
        const uint32_t dst = smb + ((seq & 1) ? BP1 : BP0)
                           + (uint32_t)(row * (PSTR * 2) + hfl * 2);
        const __half* src = wf + (size_t)row * KW + koff + hfl;
        #pragma unroll
        for (int j = 0; j < 4; j++) cpa16(dst + j * 16, src + j * 8);
    };

    // ---- warp tiling ----
    const int m0 = (wid >> 2) * 64, n0 = (wid & 3) * 32;
    const int rowA = (lane & 7) + 8 * ((lane >> 3) & 1), kA = 8 * (lane >> 4);
    const int rowB = (lane & 7) + 8 * ((lane >> 4) & 1), kB = 8 * ((lane >> 3) & 1);
    const int g = lane >> 2, t4 = lane & 3;

    float acc[4][4][4];
    #pragma unroll
    for (int a = 0; a < 4; a++)
        #pragma unroll
        for (int b = 0; b < 4; b++)
            #pragma unroll
            for (int c = 0; c < 4; c++) acc[a][b][c] = 0.0f;

    // ---- prologue ----
    issueRAW(0); stageB(0); CP_COMMIT;
    CP_WAIT0;
    splitRAW((!IS_EDGE && 0 >= 2) ? invc_reg : 1.0f);
    issueRAW(1); stageB(1); CP_COMMIT;
    __syncthreads();

    // ---- GEMM1 pipeline ----
    for (int s = 0; s < NS; s++) {
        gemm_slab32(acc, smb, APH, APL, (s & 1) ? BP1 : BP0,
                    m0, n0, rowA, kA, rowB, kB);
        __syncthreads();
        CP_WAIT0;
        if (s + 1 < NS) {
            splitRAW((!IS_EDGE && (s + 1) >= 2) ? invc_reg : 1.0f);
            issueRAW(s + 2);
        }
        stageB(s + 2);
        CP_COMMIT;
        __syncthreads();
    }

    // ---- hidden: bias+relu; cols<64 -> A panels (split), cols>=64 -> RAW f32 ----
    #pragma unroll
    for (int mt = 0; mt < 4; mt++) {
        const int r1 = m0 + mt * 16 + g, r2 = r1 + 8;
        #pragma unroll
        for (int na = 0; na < 4; na++) {
            const int c = n0 + na * 8 + 2 * t4;
            float h00 = fmaxf(acc[mt][na][0] + sb1[c],     0.0f);
            float h01 = fmaxf(acc[mt][na][1] + sb1[c + 1], 0.0f);
            float h10 = fmaxf(acc[mt][na][2] + sb1[c],     0.0f);
            float h11 = fmaxf(acc[mt][na][3] + sb1[c + 1], 0.0f);
            if (n0 < 64) {
                uint32_t hw0, lw0, hw1, lw1;
                split2h(h00, h01, hw0, lw0);
                split2h(h10, h11, hw1, lw1);
                *(uint32_t*)(smc + APH + (r1 * PSTR + c) * 2) = hw0;
                *(uint32_t*)(smc + APL + (r1 * PSTR + c) * 2) = lw0;
                *(uint32_t*)(smc + APH + (r2 * PSTR + c) * 2) = hw1;
                *(uint32_t*)(smc + APL + (r2 * PSTR + c) * 2) = lw1;
            } else {
                const int cc = c - 64;
                *(float2*)(smc + RAWOFF + SW128(r1 * 256 + cc * 4)) = make_float2(h00, h01);
                *(float2*)(smc + RAWOFF + SW128(r2 * 256 + cc * 4)) = make_float2(h10, h11);
            }
            acc[mt][na][0] = acc[mt][na][1] = acc[mt][na][2] = acc[mt][na][3] = 0.0f;
        }
    }
    CP_WAIT0;                        // W2 slab1 landed
    __syncthreads();

    // ---- GEMM2 slab0: H[:, :64] @ W2[:64] ----
    gemm_slab32(acc, smb, APH, APL, (NS & 1) ? BP1 : BP0,
                m0, n0, rowA, kA, rowB, kB);
    __syncthreads();
    // split H[:, 64:] from RAW into A panels
    splitRAW(1.0f);
    __syncthreads();
    // ---- GEMM2 slab1 ----
    gemm_slab32(acc, smb, APH, APL, ((NS + 1) & 1) ? BP1 : BP0,
                m0, n0, rowA, kA, rowB, kB);

    // ---- epilogue: bias -> store (+ atomic scatter for edge) ----
    #pragma unroll
    for (int mt = 0; mt < 4; mt++) {
        const int r1 = m0 + mt * 16 + g, r2 = r1 + 8;
        #pragma unroll
        for (int na = 0; na < 4; na++) {
            const int c = n0 + na * 8 + 2 * t4;
            const float b0 = sb2[c], b1 = sb2[c + 1];
            float v00 = acc[mt][na][0] + b0, v01 = acc[mt][na][1] + b1;
            float v10 = acc[mt][na][2] + b0, v11 = acc[mt][na][3] + b1;
            if (IS_EDGE) {
                *(float2*)(outp + (size_t)(r0 + r1) * 128 + c) = make_float2(v00, v01);
                *(float2*)(outp + (size_t)(r0 + r2) * 128 + c) = make_float2(v10, v11);
                float* a1 = g_agg + (size_t)rs[r1] * 128 + c;
                float* a2 = g_agg + (size_t)rs[r2] * 128 + c;
                atomicAdd(a1, v00); atomicAdd(a1 + 1, v01);
                atomicAdd(a2, v10); atomicAdd(a2 + 1, v11);
            } else {
                if (r0 + r1 < NN)
                    *(float2*)(outp + (size_t)(r0 + r1) * 128 + c) = make_float2(v00, v01);
                if (r0 + r2 < NN)
                    *(float2*)(outp + (size_t)(r0 + r2) * 128 + c) = make_float2(v10, v11);
            }
        }
    }
    if (IS_EDGE && (wid & 3) == 0 && t4 == 0) {
        #pragma unroll
        for (int mt = 0; mt < 4; mt++) {
            atomicAdd(g_cnt + rs[m0 + mt * 16 + g],     1.0f);
            atomicAdd(g_cnt + rs[m0 + mt * 16 + g + 8], 1.0f);
        }
    }
}

// ============================= launch =============================
extern "C" void kernel_launch(void* const* d_in, const int* in_sizes, int n_in,
                              void* d_out, int out_size) {
    const float* x   = (const float*)d_in[0];
    const void*  ei  = d_in[1];
    const float* ea  = (const float*)d_in[2];
    const float* be1 = (const float*)d_in[4];
    const float* be2 = (const float*)d_in[6];
    const float* bn1 = (const float*)d_in[8];
    const float* bn2 = (const float*)d_in[10];

    float* out      = (float*)d_out;
    float* x_out    = out;                       // [NN, 128]
    float* edge_out = out + (size_t)NN * 128;    // [NE, 128]

    cudaFuncSetAttribute(mlp_kernel<true>,  cudaFuncAttributeMaxDynamicSharedMemorySize, SMEM_TOTAL);
    cudaFuncSetAttribute(mlp_kernel<false>, cudaFuncAttributeMaxDynamicSharedMemorySize, SMEM_TOTAL);

    detect_kernel<<<1, 32>>>((const int*)ei);
    zero_kernel<<<2048, 256>>>();
    prep_kernel<<<448, 256>>>((const float*)d_in[3], (const float*)d_in[5],
                              (const float*)d_in[7], (const float*)d_in[9]);
    mlp_kernel<true><<<NE / 128, 256, SMEM_TOTAL>>>(x, ei, ea, be1, be2, edge_out);
    mlp_kernel<false><<<(NN + 127) / 128, 256, SMEM_TOTAL>>>(x, ei, ea, bn1, bn2, x_out);
}

// round 11
// speedup vs baseline: 5.6065x; 1.1858x over previous
#include <cuda_runtime.h>
#include <cuda_fp16.h>
#include <cstdint>

#define NN 50000
#define NE 640000
#define PSTR 72

// ============================= device scratch =============================
__device__ __align__(16) float g_agg[(size_t)NN * 128];
__device__ float g_cnt[NN];
__device__ int   g_is64;
// pre-transposed fp16 weights: WT[n][k] = (half)W[k][n]
__device__ __align__(16) __half g_W1f[128 * 384];
__device__ __align__(16) __half g_W2f[128 * 128];
__device__ __align__(16) __half g_N1f[128 * 256];
__device__ __align__(16) __half g_N2f[128 * 128];

// ============================= helpers =============================
__device__ __forceinline__ uint32_t smem_to_u32(const void* p) {
    uint32_t a;
    asm("{ .reg .u64 t; cvta.to.shared.u64 t, %1; cvt.u32.u64 %0, t; }" : "=r"(a) : "l"(p));
    return a;
}
__device__ __forceinline__ void ldsm4(uint32_t* r, uint32_t addr) {
    asm volatile("ldmatrix.sync.aligned.m8n8.x4.shared.b16 {%0,%1,%2,%3}, [%4];"
                 : "=r"(r[0]), "=r"(r[1]), "=r"(r[2]), "=r"(r[3]) : "r"(addr));
}
__device__ __forceinline__ void mma16816(float* c, const uint32_t* a,
                                         uint32_t b0, uint32_t b1) {
    asm volatile(
        "mma.sync.aligned.m16n8k16.row.col.f32.f16.f16.f32 "
        "{%0,%1,%2,%3}, {%4,%5,%6,%7}, {%8,%9}, {%0,%1,%2,%3};"
        : "+f"(c[0]), "+f"(c[1]), "+f"(c[2]), "+f"(c[3])
        : "r"(a[0]), "r"(a[1]), "r"(a[2]), "r"(a[3]), "r"(b0), "r"(b1));
}
__device__ __forceinline__ void cpa16(uint32_t dst, const void* src) {
    asm volatile("cp.async.cg.shared.global [%0], [%1], 16;" :: "r"(dst), "l"(src));
}
#define CP_COMMIT asm volatile("cp.async.commit_group;" ::: "memory")
#define CP_WAIT0  asm volatile("cp.async.wait_group 0;"  ::: "memory")
#define SW128(o) ((o) ^ (((o) >> 3) & 0x70))

// pack two floats -> fp16x2 word (single precision pass)
__device__ __forceinline__ uint32_t pack2h(float a, float b) {
    __half2 h2; h2.x = __float2half(a); h2.y = __float2half(b);
    return *reinterpret_cast<uint32_t*>(&h2);
}
__device__ __forceinline__ long long load_idx(const void* ei, long long pos, int is64) {
    return is64 ? ((const long long*)ei)[pos] : (long long)((const int*)ei)[pos];
}

// ============================= SMEM layout (bytes) =============================
#define SM_RS   0            // 128 ints
#define SM_B1   2048         // bias1 [128] f32
#define SM_B2   2560         // bias2 [128] f32
// A panel (single fp16): 128 rows x PSTR halves = 18432 B
#define APH     4096
// B fp16 double buffer: 128 rows x PSTR halves
#define BP0     22528
#define BP1     40960
// raw fp32 slab: 128 rows x 64 f32, swizzled (also holds H cols 64..127 later)
#define RAWOFF  59392
#define SMEM_TOTAL 92160     // 2 CTAs/SM: 184320 <= 227KB

// ============================= utility kernels =============================
__global__ void zero_kernel() {
    size_t stride = (size_t)gridDim.x * blockDim.x;
    for (size_t i = (size_t)blockIdx.x * blockDim.x + threadIdx.x;
         i < (size_t)NN * 128; i += stride) {
        g_agg[i] = 0.0f;
        if (i < NN) g_cnt[i] = 0.0f;
    }
}
__global__ void detect_kernel(const int* ei32) {
    if (threadIdx.x == 0 && blockIdx.x == 0) {
        int is64 = 1;
        for (int i = 0; i < 128; i++)
            if (ei32[2 * i + 1] != 0) { is64 = 0; break; }
        g_is64 = is64;
    }
}
__global__ void prep_kernel(const float* We1, const float* We2,
                            const float* Wn1, const float* Wn2) {
    int i = blockIdx.x * blockDim.x + threadIdx.x;
    if (i < 49152) {                       // We1 [384][128] -> WT [128][384]
        int k = i / 128, n = i % 128;
        g_W1f[n * 384 + k] = __float2half(We1[i]);
    } else if (i < 65536) {
        int j = i - 49152; int k = j / 128, n = j % 128;
        g_W2f[n * 128 + k] = __float2half(We2[j]);
    } else if (i < 98304) {
        int j = i - 65536; int k = j / 128, n = j % 128;
        g_N1f[n * 256 + k] = __float2half(Wn1[j]);
    } else if (i < 114688) {
        int j = i - 98304; int k = j / 128, n = j % 128;
        g_N2f[n * 128 + k] = __float2half(Wn2[j]);
    }
}

// ============================= GEMM slab (K=64), warp tile 64x32, fp16 1-pass ============
__device__ __forceinline__ void gemm_slab32(
    float acc[4][4][4], uint32_t smb,
    uint32_t aP, uint32_t bP,
    int m0, int n0, int rowA, int kA, int rowB, int kB)
{
    #pragma unroll
    for (int k16 = 0; k16 < 4; k16++) {
        const int kk = k16 * 16;
        uint32_t ah[4][4], bb[2][4];
        #pragma unroll
        for (int mt = 0; mt < 4; mt++)
            ldsm4(ah[mt], smb + aP + (uint32_t)(((m0 + mt * 16 + rowA) * PSTR + kk + kA) * 2));
        #pragma unroll
        for (int np = 0; np < 2; np++)
            ldsm4(bb[np], smb + bP + (uint32_t)(((n0 + np * 16 + rowB) * PSTR + kk + kB) * 2));
        #pragma unroll
        for (int mt = 0; mt < 4; mt++)
            #pragma unroll
            for (int na = 0; na < 4; na++)
                mma16816(acc[mt][na], ah[mt], bb[na >> 1][(na & 1) * 2], bb[na >> 1][(na & 1) * 2 + 1]);
    }
}

// ============================= fused MLP kernel =============================
// CTA: 128 rows x 128 out, 256 thr, 8 warps (2m x 4n), warp tile 64x32, 2 CTAs/SM.
template <bool IS_EDGE>
__global__ void __launch_bounds__(256, 2) mlp_kernel(
    const float* __restrict__ x, const void* __restrict__ ei,
    const float* __restrict__ ea,
    const float* __restrict__ b1v, const float* __restrict__ b2v,
    float* __restrict__ outp)
{
    extern __shared__ char smc[];
    const uint32_t smb = smem_to_u32(smc);
    const int tid = threadIdx.x;
    const int wid = tid >> 5, lane = tid & 31;
    const long long r0 = (long long)blockIdx.x * 128;
    const int NS = IS_EDGE ? 6 : 4;

    int*   rs  = (int*)(smc + SM_RS);
    float* sb1 = (float*)(smc + SM_B1);
    float* sb2 = (float*)(smc + SM_B2);

    // thread pair (tid, tid^1) shares row = tid>>1; half index (tid&1)
    const int row = tid >> 1, hfl = (tid & 1) * 32;   // hfl in f32/half units
    const float* aBase[3];
    float invc_reg = 1.0f;
    if (IS_EDGE) {
        const int is64 = g_is64;
        long long rr = load_idx(ei, r0 + row, is64);
        long long cc = load_idx(ei, (long long)NE + r0 + row, is64);
        rs[row] = (int)rr;
        aBase[0] = x + (size_t)rr * 128;
        aBase[1] = x + (size_t)cc * 128;
        aBase[2] = ea + (size_t)(r0 + row) * 128;
    } else {
        long long nd = r0 + row; if (nd > NN - 1) nd = NN - 1;
        invc_reg = 1.0f / fmaxf(g_cnt[nd], 1.0f);
        aBase[0] = x + (size_t)nd * 128;
        aBase[1] = g_agg + (size_t)nd * 128;
        aBase[2] = g_agg + (size_t)nd * 128;
    }
    if (tid < 128) { sb1[tid] = b1v[tid]; sb2[tid] = b2v[tid]; }

    // ---- staging lambdas ----
    auto issueRAW = [&](int s) {     // raw fp32 slab s -> RAW (swizzled)
        if (s >= NS) return;
        const float* p = aBase[s >> 1] + (s & 1) * 64 + hfl;
        #pragma unroll
        for (int j = 0; j < 8; j++)
            cpa16(smb + RAWOFF + SW128(row * 256 + hfl * 4 + j * 16), p + j * 4);
    };
    auto cvtRAW = [&](float sc) {    // RAW f32 -> A fp16 panel (single pass)
        #pragma unroll
        for (int j = 0; j < 4; j++) {
            float4 v0 = *(const float4*)(smc + RAWOFF + SW128(row * 256 + hfl * 4 + j * 32));
            float4 v1 = *(const float4*)(smc + RAWOFF + SW128(row * 256 + hfl * 4 + j * 32 + 16));
            uint32_t h0 = pack2h(v0.x * sc, v0.y * sc);
            uint32_t h1 = pack2h(v0.z * sc, v0.w * sc);
            uint32_t h2 = pack2h(v1.x * sc, v1.y * sc);
            uint32_t h3 = pack2h(v1.z * sc, v1.w * sc);
            const int ob = row * (PSTR * 2) + hfl * 2 + j * 16;
            *(uint4*)(smc + APH + ob) = make_uint4(h0, h1, h2, h3);
        }
    };
    auto stageB = [&](int seq) {     // weight slab seq -> buf[seq&1]
        if (seq > NS + 1) return;
        const __half* wf; int KW, koff;
        if (seq < NS) {
            wf = IS_EDGE ? g_W1f : g_N1f;
            KW = IS_EDGE ? 384 : 256; koff = seq * 64;
        } else {
            wf = IS_EDGE ? g_W2f : g_N2f;
            KW = 128; koff = (seq - NS) * 64;
        }
        const uint32_t dst = smb + ((seq & 1) ? BP1 : BP0)
                           + (uint32_t)(row * (PSTR * 2) + hfl * 2);
        const __half* src = wf + (size_t)row * KW + koff + hfl;
        #pragma unroll
        for (int j = 0; j < 4; j++) cpa16(dst + j * 16, src + j * 8);
    };

    // ---- warp tiling ----
    const int m0 = (wid >> 2) * 64, n0 = (wid & 3) * 32;
    const int rowA = (lane & 7) + 8 * ((lane >> 3) & 1), kA = 8 * (lane >> 4);
    const int rowB = (lane & 7) + 8 * ((lane >> 4) & 1), kB = 8 * ((lane >> 3) & 1);
    const int g = lane >> 2, t4 = lane & 3;

    float acc[4][4][4];
    #pragma unroll
    for (int a = 0; a < 4; a++)
        #pragma unroll
        for (int b = 0; b < 4; b++)
            #pragma unroll
            for (int c = 0; c < 4; c++) acc[a][b][c] = 0.0f;

    // ---- prologue ----
    issueRAW(0); stageB(0); CP_COMMIT;
    CP_WAIT0;
    cvtRAW(1.0f);
    issueRAW(1); stageB(1); CP_COMMIT;
    __syncthreads();

    // ---- GEMM1 pipeline ----
    for (int s = 0; s < NS; s++) {
        gemm_slab32(acc, smb, APH, (s & 1) ? BP1 : BP0,
                    m0, n0, rowA, kA, rowB, kB);
        __syncthreads();
        CP_WAIT0;
        if (s + 1 < NS) {
            cvtRAW((!IS_EDGE && (s + 1) >= 2) ? invc_reg : 1.0f);
            issueRAW(s + 2);
        }
        stageB(s + 2);
        CP_COMMIT;
        __syncthreads();
    }

    // ---- hidden: bias+relu; cols<64 -> A panel fp16, cols>=64 -> RAW f32 ----
    #pragma unroll
    for (int mt = 0; mt < 4; mt++) {
        const int r1 = m0 + mt * 16 + g, r2 = r1 + 8;
        #pragma unroll
        for (int na = 0; na < 4; na++) {
            const int c = n0 + na * 8 + 2 * t4;
            float h00 = fmaxf(acc[mt][na][0] + sb1[c],     0.0f);
            float h01 = fmaxf(acc[mt][na][1] + sb1[c + 1], 0.0f);
            float h10 = fmaxf(acc[mt][na][2] + sb1[c],     0.0f);
            float h11 = fmaxf(acc[mt][na][3] + sb1[c + 1], 0.0f);
            if (n0 < 64) {
                *(uint32_t*)(smc + APH + (r1 * PSTR + c) * 2) = pack2h(h00, h01);
                *(uint32_t*)(smc + APH + (r2 * PSTR + c) * 2) = pack2h(h10, h11);
            } else {
                const int cc = c - 64;
                *(float2*)(smc + RAWOFF + SW128(r1 * 256 + cc * 4)) = make_float2(h00, h01);
                *(float2*)(smc + RAWOFF + SW128(r2 * 256 + cc * 4)) = make_float2(h10, h11);
            }
            acc[mt][na][0] = acc[mt][na][1] = acc[mt][na][2] = acc[mt][na][3] = 0.0f;
        }
    }
    CP_WAIT0;                        // W2 slab1 landed
    __syncthreads();

    // ---- GEMM2 slab0: H[:, :64] @ W2[:64] ----
    gemm_slab32(acc, smb, APH, (NS & 1) ? BP1 : BP0,
                m0, n0, rowA, kA, rowB, kB);
    __syncthreads();
    // convert H[:, 64:] from RAW into A panel
    cvtRAW(1.0f);
    __syncthreads();
    // ---- GEMM2 slab1 ----
    gemm_slab32(acc, smb, APH, ((NS + 1) & 1) ? BP1 : BP0,
                m0, n0, rowA, kA, rowB, kB);

    // ---- epilogue: bias -> store (+ atomic scatter for edge) ----
    #pragma unroll
    for (int mt = 0; mt < 4; mt++) {
        const int r1 = m0 + mt * 16 + g, r2 = r1 + 8;
        #pragma unroll
        for (int na = 0; na < 4; na++) {
            const int c = n0 + na * 8 + 2 * t4;
            const float b0 = sb2[c], b1 = sb2[c + 1];
            float v00 = acc[mt][na][0] + b0, v01 = acc[mt][na][1] + b1;
            float v10 = acc[mt][na][2] + b0, v11 = acc[mt][na][3] + b1;
            if (IS_EDGE) {
                *(float2*)(outp + (size_t)(r0 + r1) * 128 + c) = make_float2(v00, v01);
                *(float2*)(outp + (size_t)(r0 + r2) * 128 + c) = make_float2(v10, v11);
                float* a1 = g_agg + (size_t)rs[r1] * 128 + c;
                float* a2 = g_agg + (size_t)rs[r2] * 128 + c;
                atomicAdd(a1, v00); atomicAdd(a1 + 1, v01);
                atomicAdd(a2, v10); atomicAdd(a2 + 1, v11);
            } else {
                if (r0 + r1 < NN)
                    *(float2*)(outp + (size_t)(r0 + r1) * 128 + c) = make_float2(v00, v01);
                if (r0 + r2 < NN)
                    *(float2*)(outp + (size_t)(r0 + r2) * 128 + c) = make_float2(v10, v11);
            }
        }
    }
    if (IS_EDGE && (wid & 3) == 0 && t4 == 0) {
        #pragma unroll
        for (int mt = 0; mt < 4; mt++) {
            atomicAdd(g_cnt + rs[m0 + mt * 16 + g],     1.0f);
            atomicAdd(g_cnt + rs[m0 + mt * 16 + g + 8], 1.0f);
        }
    }
}

// ============================= launch =============================
extern "C" void kernel_launch(void* const* d_in, const int* in_sizes, int n_in,
                              void* d_out, int out_size) {
    const float* x   = (const float*)d_in[0];
    const void*  ei  = d_in[1];
    const float* ea  = (const float*)d_in[2];
    const float* be1 = (const float*)d_in[4];
    const float* be2 = (const float*)d_in[6];
    const float* bn1 = (const float*)d_in[8];
    const float* bn2 = (const float*)d_in[10];

    float* out      = (float*)d_out;
    float* x_out    = out;                       // [NN, 128]
    float* edge_out = out + (size_t)NN * 128;    // [NE, 128]

    cudaFuncSetAttribute(mlp_kernel<true>,  cudaFuncAttributeMaxDynamicSharedMemorySize, SMEM_TOTAL);
    cudaFuncSetAttribute(mlp_kernel<false>, cudaFuncAttributeMaxDynamicSharedMemorySize, SMEM_TOTAL);

    detect_kernel<<<1, 32>>>((const int*)ei);
    zero_kernel<<<2048, 256>>>();
    prep_kernel<<<448, 256>>>((const float*)d_in[3], (const float*)d_in[5],
                              (const float*)d_in[7], (const float*)d_in[9]);
    mlp_kernel<true><<<NE / 128, 256, SMEM_TOTAL>>>(x, ei, ea, be1, be2, edge_out);
    mlp_kernel<false><<<(NN + 127) / 128, 256, SMEM_TOTAL>>>(x, ei, ea, bn1, bn2, x_out);
}

// round 12
// speedup vs baseline: 5.9434x; 1.0601x over previous
#include <cuda_runtime.h>
#include <cuda_fp16.h>
#include <cstdint>

#define NN 50000
#define NE 640000
#define PSTR 72

// ============================= device scratch =============================
__device__ __align__(16) float g_agg[(size_t)NN * 128];
__device__ float g_cnt[NN];
__device__ int   g_is64;
// pre-transposed fp16 weights: WT[n][k] = (half)W[k][n]
__device__ __align__(16) __half g_W1f[128 * 384];
__device__ __align__(16) __half g_W2f[128 * 128];
__device__ __align__(16) __half g_N1f[128 * 256];
__device__ __align__(16) __half g_N2f[128 * 128];

// ============================= helpers =============================
__device__ __forceinline__ uint32_t smem_to_u32(const void* p) {
    uint32_t a;
    asm("{ .reg .u64 t; cvta.to.shared.u64 t, %1; cvt.u32.u64 %0, t; }" : "=r"(a) : "l"(p));
    return a;
}
__device__ __forceinline__ void ldsm4(uint32_t* r, uint32_t addr) {
    asm volatile("ldmatrix.sync.aligned.m8n8.x4.shared.b16 {%0,%1,%2,%3}, [%4];"
                 : "=r"(r[0]), "=r"(r[1]), "=r"(r[2]), "=r"(r[3]) : "r"(addr));
}
__device__ __forceinline__ void mma16816(float* c, const uint32_t* a,
                                         uint32_t b0, uint32_t b1) {
    asm volatile(
        "mma.sync.aligned.m16n8k16.row.col.f32.f16.f16.f32 "
        "{%0,%1,%2,%3}, {%4,%5,%6,%7}, {%8,%9}, {%0,%1,%2,%3};"
        : "+f"(c[0]), "+f"(c[1]), "+f"(c[2]), "+f"(c[3])
        : "r"(a[0]), "r"(a[1]), "r"(a[2]), "r"(a[3]), "r"(b0), "r"(b1));
}
__device__ __forceinline__ void cpa16(uint32_t dst, const void* src) {
    asm volatile("cp.async.cg.shared.global [%0], [%1], 16;" :: "r"(dst), "l"(src));
}
#define CP_COMMIT asm volatile("cp.async.commit_group;" ::: "memory")
#define CP_WAIT0  asm volatile("cp.async.wait_group 0;"  ::: "memory")
#define CP_WAIT1  asm volatile("cp.async.wait_group 1;"  ::: "memory")

// pack two floats -> fp16x2 word
__device__ __forceinline__ uint32_t pack2h(float a, float b) {
    __half2 h2; h2.x = __float2half(a); h2.y = __float2half(b);
    return *reinterpret_cast<uint32_t*>(&h2);
}
__device__ __forceinline__ long long load_idx(const void* ei, long long pos, int is64) {
    return is64 ? ((const long long*)ei)[pos] : (long long)((const int*)ei)[pos];
}

// ============================= SMEM layout (bytes) =============================
#define SM_RS   0            // 128 ints
#define SM_B1   2048         // bias1 [128] f32
#define SM_B2   2560         // bias2 [128] f32
// A fp16 panels (double buffer): 128 rows x PSTR halves = 18432 B each
#define APB(b)  (4096 + (b) * 18432)
// B fp16 panels (triple buffer)
#define BPB(b)  (40960 + (b) * 18432)
#define SMEM_TOTAL 96256     // 2 CTAs/SM

// ============================= utility kernels =============================
__global__ void zero_kernel() {
    size_t stride = (size_t)gridDim.x * blockDim.x;
    for (size_t i = (size_t)blockIdx.x * blockDim.x + threadIdx.x;
         i < (size_t)NN * 128; i += stride) {
        g_agg[i] = 0.0f;
        if (i < NN) g_cnt[i] = 0.0f;
    }
}
__global__ void detect_kernel(const int* ei32) {
    if (threadIdx.x == 0 && blockIdx.x == 0) {
        int is64 = 1;
        for (int i = 0; i < 128; i++)
            if (ei32[2 * i + 1] != 0) { is64 = 0; break; }
        g_is64 = is64;
    }
}
__global__ void prep_kernel(const float* We1, const float* We2,
                            const float* Wn1, const float* Wn2) {
    int i = blockIdx.x * blockDim.x + threadIdx.x;
    if (i < 49152) {                       // We1 [384][128] -> WT [128][384]
        int k = i / 128, n = i % 128;
        g_W1f[n * 384 + k] = __float2half(We1[i]);
    } else if (i < 65536) {
        int j = i - 49152; int k = j / 128, n = j % 128;
        g_W2f[n * 128 + k] = __float2half(We2[j]);
    } else if (i < 98304) {
        int j = i - 65536; int k = j / 128, n = j % 128;
        g_N1f[n * 256 + k] = __float2half(Wn1[j]);
    } else if (i < 114688) {
        int j = i - 98304; int k = j / 128, n = j % 128;
        g_N2f[n * 128 + k] = __float2half(Wn2[j]);
    }
}

// ============================= GEMM slab (K=64), warp tile 64x32, fp16 1-pass ============
__device__ __forceinline__ void gemm_slab32(
    float acc[4][4][4], uint32_t smb,
    uint32_t aP, uint32_t bP,
    int m0, int n0, int rowA, int kA, int rowB, int kB)
{
    #pragma unroll
    for (int k16 = 0; k16 < 4; k16++) {
        const int kk = k16 * 16;
        uint32_t ah[4][4], bb[2][4];
        #pragma unroll
        for (int mt = 0; mt < 4; mt++)
            ldsm4(ah[mt], smb + aP + (uint32_t)(((m0 + mt * 16 + rowA) * PSTR + kk + kA) * 2));
        #pragma unroll
        for (int np = 0; np < 2; np++)
            ldsm4(bb[np], smb + bP + (uint32_t)(((n0 + np * 16 + rowB) * PSTR + kk + kB) * 2));
        #pragma unroll
        for (int mt = 0; mt < 4; mt++)
            #pragma unroll
            for (int na = 0; na < 4; na++)
                mma16816(acc[mt][na], ah[mt], bb[na >> 1][(na & 1) * 2], bb[na >> 1][(na & 1) * 2 + 1]);
    }
}

// ============================= fused MLP kernel =============================
// CTA: 128 rows x 128 out, 256 thr, 8 warps (2m x 4n), warp tile 64x32, 2 CTAs/SM.
// Single-sync slab pipeline: A double-buffered fp16 (direct LDG gather), B triple-buffered.
template <bool IS_EDGE>
__global__ void __launch_bounds__(256, 2) mlp_kernel(
    const float* __restrict__ x, const void* __restrict__ ei,
    const float* __restrict__ ea,
    const float* __restrict__ b1v, const float* __restrict__ b2v,
    float* __restrict__ outp)
{
    extern __shared__ char smc[];
    const uint32_t smb = smem_to_u32(smc);
    const int tid = threadIdx.x;
    const int wid = tid >> 5, lane = tid & 31;
    const long long r0 = (long long)blockIdx.x * 128;
    const int NS = IS_EDGE ? 6 : 4;

    int*   rs  = (int*)(smc + SM_RS);
    float* sb1 = (float*)(smc + SM_B1);
    float* sb2 = (float*)(smc + SM_B2);

    // thread pair shares row = tid>>1; half index (tid&1): 32 floats each
    const int row = tid >> 1, hfl = (tid & 1) * 32;
    const float* aBase[3];
    float invc_reg = 1.0f;
    if (IS_EDGE) {
        const int is64 = g_is64;
        long long rr = load_idx(ei, r0 + row, is64);
        long long cc = load_idx(ei, (long long)NE + r0 + row, is64);
        rs[row] = (int)rr;
        aBase[0] = x + (size_t)rr * 128;
        aBase[1] = x + (size_t)cc * 128;
        aBase[2] = ea + (size_t)(r0 + row) * 128;
    } else {
        long long nd = r0 + row; if (nd > NN - 1) nd = NN - 1;
        invc_reg = 1.0f / fmaxf(g_cnt[nd], 1.0f);
        aBase[0] = x + (size_t)nd * 128;
        aBase[1] = g_agg + (size_t)nd * 128;
        aBase[2] = g_agg + (size_t)nd * 128;
    }
    if (tid < 128) { sb1[tid] = b1v[tid]; sb2[tid] = b2v[tid]; }

    // ---- staging helpers ----
    auto ldgA = [&](int s, float4* v) {      // gather 32 floats of slab s
        const float* p = aBase[s >> 1] + (s & 1) * 64 + hfl;
        #pragma unroll
        for (int j = 0; j < 8; j++) v[j] = *(const float4*)(p + j * 4);
    };
    auto stsA = [&](int s, const float4* v) { // convert + store into A[s&1]
        const float sc = (!IS_EDGE && s >= 2) ? invc_reg : 1.0f;
        const int ob = row * (PSTR * 2) + hfl * 2;
        #pragma unroll
        for (int j = 0; j < 4; j++) {
            uint32_t w0 = pack2h(v[2 * j].x * sc,     v[2 * j].y * sc);
            uint32_t w1 = pack2h(v[2 * j].z * sc,     v[2 * j].w * sc);
            uint32_t w2 = pack2h(v[2 * j + 1].x * sc, v[2 * j + 1].y * sc);
            uint32_t w3 = pack2h(v[2 * j + 1].z * sc, v[2 * j + 1].w * sc);
            *(uint4*)(smc + APB(s & 1) + ob + j * 16) = make_uint4(w0, w1, w2, w3);
        }
    };
    auto stageB = [&](int seq) {              // weight slab seq -> B[seq%3]
        if (seq > NS + 1) return;
        const __half* wf; int KW, koff;
        if (seq < NS) {
            wf = IS_EDGE ? g_W1f : g_N1f;
            KW = IS_EDGE ? 384 : 256; koff = seq * 64;
        } else {
            wf = IS_EDGE ? g_W2f : g_N2f;
            KW = 128; koff = (seq - NS) * 64;
        }
        const uint32_t dst = smb + BPB(seq % 3)
                           + (uint32_t)(row * (PSTR * 2) + hfl * 2);
        const __half* src = wf + (size_t)row * KW + koff + hfl;
        #pragma unroll
        for (int j = 0; j < 4; j++) cpa16(dst + j * 16, src + j * 8);
    };

    // ---- warp tiling ----
    const int m0 = (wid >> 2) * 64, n0 = (wid & 3) * 32;
    const int rowA = (lane & 7) + 8 * ((lane >> 3) & 1), kA = 8 * (lane >> 4);
    const int rowB = (lane & 7) + 8 * ((lane >> 4) & 1), kB = 8 * ((lane >> 3) & 1);
    const int g = lane >> 2, t4 = lane & 3;

    float acc[4][4][4];
    #pragma unroll
    for (int a = 0; a < 4; a++)
        #pragma unroll
        for (int b = 0; b < 4; b++)
            #pragma unroll
            for (int c = 0; c < 4; c++) acc[a][b][c] = 0.0f;

    // ---- prologue: B(0), B(1) in flight; A(0) direct ----
    stageB(0); CP_COMMIT;
    stageB(1); CP_COMMIT;
    {
        float4 v[8];
        ldgA(0, v);
        stsA(0, v);
    }
    CP_WAIT1;                 // B(0) landed
    __syncthreads();

    // ---- GEMM1: single-sync pipeline ----
    for (int s = 0; s < NS; s++) {
        float4 v[8];
        if (s + 1 < NS) ldgA(s + 1, v);           // gather overlaps gemm below
        gemm_slab32(acc, smb, APB(s & 1), BPB(s % 3),
                    m0, n0, rowA, kA, rowB, kB);
        if (s + 1 < NS) stsA(s + 1, v);           // writes other A buffer
        stageB(s + 2); CP_COMMIT;
        CP_WAIT1;                                  // B(s+1) landed
        __syncthreads();
    }

    // ---- hidden: bias+relu -> fp16; cols<64 -> A[0], cols>=64 -> A[1] ----
    #pragma unroll
    for (int mt = 0; mt < 4; mt++) {
        const int r1 = m0 + mt * 16 + g, r2 = r1 + 8;
        #pragma unroll
        for (int na = 0; na < 4; na++) {
            const int c = n0 + na * 8 + 2 * t4;
            float h00 = fmaxf(acc[mt][na][0] + sb1[c],     0.0f);
            float h01 = fmaxf(acc[mt][na][1] + sb1[c + 1], 0.0f);
            float h10 = fmaxf(acc[mt][na][2] + sb1[c],     0.0f);
            float h11 = fmaxf(acc[mt][na][3] + sb1[c + 1], 0.0f);
            const int buf = (c < 64) ? 0 : 1;
            const int cc = c & 63;
            *(uint32_t*)(smc + APB(buf) + (r1 * PSTR + cc) * 2) = pack2h(h00, h01);
            *(uint32_t*)(smc + APB(buf) + (r2 * PSTR + cc) * 2) = pack2h(h10, h11);
            acc[mt][na][0] = acc[mt][na][1] = acc[mt][na][2] = acc[mt][na][3] = 0.0f;
        }
    }
    CP_WAIT0;                 // W2 slabs landed
    __syncthreads();

    // ---- GEMM2: two back-to-back slabs, no intermediate syncs ----
    gemm_slab32(acc, smb, APB(0), BPB(NS % 3),
                m0, n0, rowA, kA, rowB, kB);
    gemm_slab32(acc, smb, APB(1), BPB((NS + 1) % 3),
                m0, n0, rowA, kA, rowB, kB);

    // ---- epilogue: bias -> store (+ atomic scatter for edge) ----
    #pragma unroll
    for (int mt = 0; mt < 4; mt++) {
        const int r1 = m0 + mt * 16 + g, r2 = r1 + 8;
        #pragma unroll
        for (int na = 0; na < 4; na++) {
            const int c = n0 + na * 8 + 2 * t4;
            const float b0 = sb2[c], b1 = sb2[c + 1];
            float v00 = acc[mt][na][0] + b0, v01 = acc[mt][na][1] + b1;
            float v10 = acc[mt][na][2] + b0, v11 = acc[mt][na][3] + b1;
            if (IS_EDGE) {
                *(float2*)(outp + (size_t)(r0 + r1) * 128 + c) = make_float2(v00, v01);
                *(float2*)(outp + (size_t)(r0 + r2) * 128 + c) = make_float2(v10, v11);
                float* a1 = g_agg + (size_t)rs[r1] * 128 + c;
                float* a2 = g_agg + (size_t)rs[r2] * 128 + c;
                atomicAdd(a1, v00); atomicAdd(a1 + 1, v01);
                atomicAdd(a2, v10); atomicAdd(a2 + 1, v11);
            } else {
                if (r0 + r1 < NN)
                    *(float2*)(outp + (size_t)(r0 + r1) * 128 + c) = make_float2(v00, v01);
                if (r0 + r2 < NN)
                    *(float2*)(outp + (size_t)(r0 + r2) * 128 + c) = make_float2(v10, v11);
            }
        }
    }
    if (IS_EDGE && (wid & 3) == 0 && t4 == 0) {
        #pragma unroll
        for (int mt = 0; mt < 4; mt++) {
            atomicAdd(g_cnt + rs[m0 + mt * 16 + g],     1.0f);
            atomicAdd(g_cnt + rs[m0 + mt * 16 + g + 8], 1.0f);
        }
    }
}

// ============================= launch =============================
extern "C" void kernel_launch(void* const* d_in, const int* in_sizes, int n_in,
                              void* d_out, int out_size) {
    const float* x   = (const float*)d_in[0];
    const void*  ei  = d_in[1];
    const float* ea  = (const float*)d_in[2];
    const float* be1 = (const float*)d_in[4];
    const float* be2 = (const float*)d_in[6];
    const float* bn1 = (const float*)d_in[8];
    const float* bn2 = (const float*)d_in[10];

    float* out      = (float*)d_out;
    float* x_out    = out;                       // [NN, 128]
    float* edge_out = out + (size_t)NN * 128;    // [NE, 128]

    cudaFuncSetAttribute(mlp_kernel<true>,  cudaFuncAttributeMaxDynamicSharedMemorySize, SMEM_TOTAL);
    cudaFuncSetAttribute(mlp_kernel<false>, cudaFuncAttributeMaxDynamicSharedMemorySize, SMEM_TOTAL);

    detect_kernel<<<1, 32>>>((const int*)ei);
    zero_kernel<<<2048, 256>>>();
    prep_kernel<<<448, 256>>>((const float*)d_in[3], (const float*)d_in[5],
                              (const float*)d_in[7], (const float*)d_in[9]);
    mlp_kernel<true><<<NE / 128, 256, SMEM_TOTAL>>>(x, ei, ea, be1, be2, edge_out);
    mlp_kernel<false><<<(NN + 127) / 128, 256, SMEM_TOTAL>>>(x, ei, ea, bn1, bn2, x_out);
}